// round 14
// baseline (speedup 1.0000x reference)
#include <cuda_runtime.h>
#include <cuda_bf16.h>
#include <math.h>
#include <stdint.h>

#define NLAYERS 16
#define DMODEL 960
#define HQ 15
#define HKV 5
#define DH 64
#define FF 2560
#define BATCH 2
#define SEQ 1024
#define MROWS (BATCH*SEQ)   // 2048
#define QDIM (HQ*DH)        // 960
#define KVDIM (HKV*DH)      // 320
#define QKVN (QDIM + 2*KVDIM) // 1600

// ---------------- scratch (no allocations allowed) ----------------
__device__ __nv_bfloat16 g_hn_h[MROWS*DMODEL];
__device__ __nv_bfloat16 g_hn_l[MROWS*DMODEL];
__device__ float         g_qkv [MROWS*QKVN];
__device__ __nv_bfloat16 g_at_h[MROWS*QDIM];
__device__ __nv_bfloat16 g_at_l[MROWS*QDIM];
__device__ __nv_bfloat16 g_ac_h[MROWS*FF];
__device__ __nv_bfloat16 g_ac_l[MROWS*FF];
// attention operands (split bf16)
__device__ __nv_bfloat16 g_qh [MROWS*QDIM];
__device__ __nv_bfloat16 g_ql [MROWS*QDIM];
__device__ __nv_bfloat16 g_kh [MROWS*KVDIM];
__device__ __nv_bfloat16 g_kl [MROWS*KVDIM];
__device__ __nv_bfloat16 g_vth[MROWS*KVDIM];
__device__ __nv_bfloat16 g_vtl[MROWS*KVDIM];
// transposed split weights, PER LAYER reused buffers ([N][K] row-major bf16)
__device__ __nv_bfloat16 g_wqkv_h[QKVN*DMODEL];
__device__ __nv_bfloat16 g_wqkv_l[QKVN*DMODEL];
__device__ __nv_bfloat16 g_wo_h [DMODEL*QDIM];
__device__ __nv_bfloat16 g_wo_l [DMODEL*QDIM];
__device__ __nv_bfloat16 g_wgu_h[2*FF*DMODEL];   // gate/up 8-col interleave
__device__ __nv_bfloat16 g_wgu_l[2*FF*DMODEL];
__device__ __nv_bfloat16 g_wd_h [DMODEL*FF];
__device__ __nv_bfloat16 g_wd_l [DMODEL*FF];

// ---------------- warp-mma helpers ----------------
__device__ __forceinline__ uint32_t smem_u32(const void* p) {
    uint32_t a;
    asm("{ .reg .u64 t; cvta.to.shared.u64 t, %1; cvt.u32.u64 %0, t; }" : "=r"(a) : "l"(p));
    return a;
}
__device__ __forceinline__ void ldm4(uint32_t* r, uint32_t addr) {
    asm volatile("ldmatrix.sync.aligned.m8n8.x4.shared.b16 {%0,%1,%2,%3}, [%4];"
        : "=r"(r[0]), "=r"(r[1]), "=r"(r[2]), "=r"(r[3]) : "r"(addr));
}
__device__ __forceinline__ void mma16816(float* c, const uint32_t* a, const uint32_t* b) {
    asm volatile("mma.sync.aligned.m16n8k16.row.col.f32.bf16.bf16.f32 "
        "{%0,%1,%2,%3}, {%4,%5,%6,%7}, {%8,%9}, {%0,%1,%2,%3};"
        : "+f"(c[0]), "+f"(c[1]), "+f"(c[2]), "+f"(c[3])
        : "r"(a[0]), "r"(a[1]), "r"(a[2]), "r"(a[3]), "r"(b[0]), "r"(b[1]));
}
__device__ __forceinline__ void cpasync16(uint32_t dst, const void* src) {
    asm volatile("cp.async.cg.shared.global [%0], [%1], 16;" :: "r"(dst), "l"(src));
}
#define CP_COMMIT() asm volatile("cp.async.commit_group;" ::: "memory")
#define CP_WAIT1()  asm volatile("cp.async.wait_group 1;" ::: "memory")
#define CP_WAIT0()  asm volatile("cp.async.wait_group 0;" ::: "memory")

__device__ __forceinline__ uint32_t packbf(float a, float b) {
    __nv_bfloat162 t = __floats2bfloat162_rn(a, b);
    return *(uint32_t*)&t;
}

// ---------------- mma GEMM 128x64 (proven core) --------------
// EPI: 0 = store fp32 C, 1 = C +=
#define STAGE_B 49152
#define GEMM_SMEM (2*STAGE_B)   // 98304

template <int EPI>
__global__ __launch_bounds__(128, 2)
void mma_gemm(const __nv_bfloat16* __restrict__ Ah, const __nv_bfloat16* __restrict__ Al,
              const __nv_bfloat16* __restrict__ Bh, const __nv_bfloat16* __restrict__ Bl,
              float* __restrict__ C, int N, int K) {
    extern __shared__ __nv_bfloat16 sm[];
    uint32_t smb = smem_u32(sm);

    int tid = threadIdx.x, wid = tid >> 5, lane = tid & 31;
    int brow = blockIdx.y * 128, bcol = blockIdx.x * 64;
    int warp_m = wid >> 1, warp_n = wid & 1;

    float acc[4][4][4];
    #pragma unroll
    for (int mt = 0; mt < 4; mt++)
        #pragma unroll
        for (int nt = 0; nt < 4; nt++)
            #pragma unroll
            for (int i = 0; i < 4; i++) acc[mt][nt][i] = 0.f;

    int tr = tid >> 3, tj = tid & 7;
    uint32_t tsw = (uint32_t)((tj ^ (tr & 7)) << 4);
    const __nv_bfloat16* gAh = Ah + (size_t)(brow + tr) * K + tj * 8;
    const __nv_bfloat16* gAl = Al + (size_t)(brow + tr) * K + tj * 8;
    const __nv_bfloat16* gBh = Bh + (size_t)(bcol + tr) * K + tj * 8;
    const __nv_bfloat16* gBl = Bl + (size_t)(bcol + tr) * K + tj * 8;

    int sxor = lane & 7;
    uint32_t aRowOff = (uint32_t)((warp_m * 64 + (lane & 15)) * 128);
    int a_cs = lane >> 4;
    uint32_t bRowOff = (uint32_t)((warp_n * 32 + (lane & 7) + ((lane >> 4) << 3)) * 128);
    int b_cs = (lane >> 3) & 1;

    int nch = K >> 6;

    {
        #pragma unroll
        for (int i = 0; i < 8; i++) {
            uint32_t d = smb + (uint32_t)((tr + 16 * i) * 128) + tsw;
            cpasync16(d,          gAh + (size_t)(16 * i) * K);
            cpasync16(d + 16384u, gAl + (size_t)(16 * i) * K);
        }
        #pragma unroll
        for (int i = 0; i < 4; i++) {
            uint32_t d = smb + 32768u + (uint32_t)((tr + 16 * i) * 128) + tsw;
            cpasync16(d,         gBh + (size_t)(16 * i) * K);
            cpasync16(d + 8192u, gBl + (size_t)(16 * i) * K);
        }
        CP_COMMIT();
    }

    for (int ch = 0; ch < nch; ch++) {
        uint32_t sbase = smb + (uint32_t)((ch & 1) ? STAGE_B : 0);
        if (ch + 1 < nch) {
            uint32_t nbase = smb + (uint32_t)(((ch + 1) & 1) ? STAGE_B : 0);
            int k0 = (ch + 1) << 6;
            #pragma unroll
            for (int i = 0; i < 8; i++) {
                uint32_t d = nbase + (uint32_t)((tr + 16 * i) * 128) + tsw;
                cpasync16(d,          gAh + (size_t)(16 * i) * K + k0);
                cpasync16(d + 16384u, gAl + (size_t)(16 * i) * K + k0);
            }
            #pragma unroll
            for (int i = 0; i < 4; i++) {
                uint32_t d = nbase + 32768u + (uint32_t)((tr + 16 * i) * 128) + tsw;
                cpasync16(d,         gBh + (size_t)(16 * i) * K + k0);
                cpasync16(d + 8192u, gBl + (size_t)(16 * i) * K + k0);
            }
            CP_COMMIT();
            CP_WAIT1();
        } else {
            CP_WAIT0();
        }
        __syncthreads();

        #pragma unroll
        for (int kk = 0; kk < 4; kk++) {
            uint32_t bCh = (uint32_t)((((kk * 2 + b_cs) ^ sxor)) << 4);
            uint32_t bAddr = sbase + 32768u + bRowOff + bCh;
            uint32_t bh[8], bl[8];
            ldm4(bh,     bAddr);
            ldm4(bh + 4, bAddr + 2048u);
            ldm4(bl,     bAddr + 8192u);
            ldm4(bl + 4, bAddr + 10240u);
            uint32_t aCh = (uint32_t)((((kk * 2 + a_cs) ^ sxor)) << 4);
            #pragma unroll
            for (int mt = 0; mt < 4; mt++) {
                uint32_t aAddr = sbase + aRowOff + (uint32_t)(mt * 2048) + aCh;
                uint32_t ah[4], al[4];
                ldm4(ah, aAddr);
                ldm4(al, aAddr + 16384u);
                #pragma unroll
                for (int nt = 0; nt < 4; nt++) {
                    mma16816(acc[mt][nt], ah, bh + 2 * nt);
                    mma16816(acc[mt][nt], ah, bl + 2 * nt);
                    mma16816(acc[mt][nt], al, bh + 2 * nt);
                }
            }
        }
        __syncthreads();
    }

    #pragma unroll
    for (int mt = 0; mt < 4; mt++) {
        int r0 = brow + warp_m * 64 + mt * 16 + (lane >> 2);
        #pragma unroll
        for (int nt = 0; nt < 4; nt++) {
            int c0 = bcol + warp_n * 32 + nt * 8 + (lane & 3) * 2;
            float* p0 = C + (size_t)r0 * N + c0;
            float* p1 = p0 + 8 * (size_t)N;
            if (EPI == 1) {
                p0[0] += acc[mt][nt][0]; p0[1] += acc[mt][nt][1];
                p1[0] += acc[mt][nt][2]; p1[1] += acc[mt][nt][3];
            } else {
                *(float2*)p0 = make_float2(acc[mt][nt][0], acc[mt][nt][1]);
                *(float2*)p1 = make_float2(acc[mt][nt][2], acc[mt][nt][3]);
            }
        }
    }
}

// ---------------- GU GEMM: 128x128 tile, BK=32, row-paired smem ----------
// 256 thr, 8 warps (2m x 4n), warp tile 64x32. 2 stages x 32KB = 64KB,
// 2 CTAs/SM. smem row i (128B) holds matrix rows (2i,2i+1); granule =
// (row&1)*4 + kc, swizzle XOR (srow&7). Fused silu(gate)*up epilogue.
#define GU2_STAGE 32768
#define GU2_SMEM (2*GU2_STAGE)   // 65536

__global__ __launch_bounds__(256, 2)
void mma_gemm_gu2(const __nv_bfloat16* __restrict__ Ah, const __nv_bfloat16* __restrict__ Al,
                  const __nv_bfloat16* __restrict__ Bh, const __nv_bfloat16* __restrict__ Bl,
                  __nv_bfloat16* __restrict__ Oh, __nv_bfloat16* __restrict__ Ol,
                  int N, int K) {
    extern __shared__ __nv_bfloat16 sm[];
    uint32_t smb = smem_u32(sm);

    int tid = threadIdx.x, wid = tid >> 5, lane = tid & 31;
    int brow = blockIdx.y * 128, bcol = blockIdx.x * 128;
    int warp_m = wid >> 2, warp_n = wid & 3;

    float acc[4][4][4];
    #pragma unroll
    for (int mt = 0; mt < 4; mt++)
        #pragma unroll
        for (int nt = 0; nt < 4; nt++)
            #pragma unroll
            for (int i = 0; i < 4; i++) acc[mt][nt][i] = 0.f;

    // producer: thread handles chunks c = tid, tid+256 of 512 (per region)
    // chunk c: matrix row mr = c>>2, 16B col-chunk kc = c&3
    int mr0 = tid >> 2, kc0 = tid & 3;
    uint32_t pb0 = (uint32_t)(((mr0 >> 1) * 128) | ((((mr0 & 1) << 2 | kc0) ^ ((mr0 >> 1) & 7)) << 4));
    int mr1 = (tid + 256) >> 2;           // = mr0 + 64
    uint32_t pb1 = (uint32_t)(((mr1 >> 1) * 128) | ((((mr1 & 1) << 2 | kc0) ^ ((mr1 >> 1) & 7)) << 4));
    const __nv_bfloat16* gA0h = Ah + (size_t)(brow + mr0) * K + kc0 * 8;
    const __nv_bfloat16* gA0l = Al + (size_t)(brow + mr0) * K + kc0 * 8;
    const __nv_bfloat16* gB0h = Bh + (size_t)(bcol + mr0) * K + kc0 * 8;
    const __nv_bfloat16* gB0l = Bl + (size_t)(bcol + mr0) * K + kc0 * 8;
    const __nv_bfloat16* gA1h = gA0h + (size_t)64 * K;
    const __nv_bfloat16* gA1l = gA0l + (size_t)64 * K;
    const __nv_bfloat16* gB1h = gB0h + (size_t)64 * K;
    const __nv_bfloat16* gB1l = gB0l + (size_t)64 * K;

    // consumer addressing
    // A: mr = warp_m*64 + (lane&15) (+16 per mt), kcA = kk*2 + (lane>>4)
    int amr = warp_m * 64 + (lane & 15);
    uint32_t aRowOff = (uint32_t)((amr >> 1) * 128);
    int aG0 = ((amr & 1) << 2) ^ ((amr >> 1) & 7);
    int a_cs = lane >> 4;
    // B: nr = warp_n*32 + (lane&7) + ((lane>>4)<<3) (+16 for 2nd ldm4)
    int bnr = warp_n * 32 + (lane & 7) + ((lane >> 4) << 3);
    uint32_t bRowOff = (uint32_t)((bnr >> 1) * 128);
    int bG0 = ((bnr & 1) << 2) ^ ((bnr >> 1) & 7);
    int b_cs = (lane >> 3) & 1;

    int nch = K >> 5;   // BK=32

    {   // prologue
        cpasync16(smb + pb0,           gA0h);
        cpasync16(smb + pb1,           gA1h);
        cpasync16(smb + 8192u + pb0,   gA0l);
        cpasync16(smb + 8192u + pb1,   gA1l);
        cpasync16(smb + 16384u + pb0,  gB0h);
        cpasync16(smb + 16384u + pb1,  gB1h);
        cpasync16(smb + 24576u + pb0,  gB0l);
        cpasync16(smb + 24576u + pb1,  gB1l);
        CP_COMMIT();
    }

    for (int ch = 0; ch < nch; ch++) {
        uint32_t sbase = smb + (uint32_t)((ch & 1) ? GU2_STAGE : 0);
        if (ch + 1 < nch) {
            uint32_t nbase = smb + (uint32_t)(((ch + 1) & 1) ? GU2_STAGE : 0);
            int k0 = (ch + 1) << 5;
            cpasync16(nbase + pb0,          gA0h + k0);
            cpasync16(nbase + pb1,          gA1h + k0);
            cpasync16(nbase + 8192u + pb0,  gA0l + k0);
            cpasync16(nbase + 8192u + pb1,  gA1l + k0);
            cpasync16(nbase + 16384u + pb0, gB0h + k0);
            cpasync16(nbase + 16384u + pb1, gB1h + k0);
            cpasync16(nbase + 24576u + pb0, gB0l + k0);
            cpasync16(nbase + 24576u + pb1, gB1l + k0);
            CP_COMMIT();
            CP_WAIT1();
        } else {
            CP_WAIT0();
        }
        __syncthreads();

        #pragma unroll
        for (int kk = 0; kk < 2; kk++) {
            uint32_t bAddr = sbase + 16384u + bRowOff + (uint32_t)((bG0 ^ (kk * 2 + b_cs)) << 4);
            uint32_t bh[8], bl[8];
            ldm4(bh,     bAddr);
            ldm4(bh + 4, bAddr + 1024u);   // +16 n-rows = +8 smem rows
            ldm4(bl,     bAddr + 8192u);
            ldm4(bl + 4, bAddr + 9216u);
            uint32_t aCh = (uint32_t)((aG0 ^ (kk * 2 + a_cs)) << 4);
            #pragma unroll
            for (int mt = 0; mt < 4; mt++) {
                uint32_t aAddr = sbase + aRowOff + (uint32_t)(mt * 1024) + aCh;
                uint32_t ah[4], al[4];
                ldm4(ah, aAddr);
                ldm4(al, aAddr + 8192u);
                #pragma unroll
                for (int nt = 0; nt < 4; nt++) {
                    mma16816(acc[mt][nt], ah, bh + 2 * nt);
                    mma16816(acc[mt][nt], ah, bl + 2 * nt);
                    mma16816(acc[mt][nt], al, bh + 2 * nt);
                }
            }
        }
        __syncthreads();
    }

    // fused silu(gate)*up epilogue (gate/up 8-col interleave in B rows)
    int NOUT = N >> 1;
    #pragma unroll
    for (int mt = 0; mt < 4; mt++) {
        int r0 = brow + warp_m * 64 + mt * 16 + (lane >> 2);
        #pragma unroll
        for (int j = 0; j < 2; j++) {
            int fcol = (bcol >> 1) + warp_n * 16 + j * 8 + (lane & 3) * 2;
            #pragma unroll
            for (int half = 0; half < 2; half++) {
                int r = r0 + half * 8;
                float g0 = acc[mt][2*j][half * 2 + 0], u0 = acc[mt][2*j+1][half * 2 + 0];
                float g1 = acc[mt][2*j][half * 2 + 1], u1 = acc[mt][2*j+1][half * 2 + 1];
                float y0 = (g0 / (1.f + __expf(-g0))) * u0;
                float y1 = (g1 / (1.f + __expf(-g1))) * u1;
                __nv_bfloat16 h0 = __float2bfloat16(y0), h1 = __float2bfloat16(y1);
                __nv_bfloat16 l0 = __float2bfloat16(y0 - __bfloat162float(h0));
                __nv_bfloat16 l1 = __float2bfloat16(y1 - __bfloat162float(h1));
                *(__nv_bfloat162*)(Oh + (size_t)r * NOUT + fcol) = __nv_bfloat162(h0, h1);
                *(__nv_bfloat162*)(Ol + (size_t)r * NOUT + fcol) = __nv_bfloat162(l0, l1);
            }
        }
    }
}

// ---------------- per-layer weight prep: 64x64 tiles, wide I/O ----------
__global__ __launch_bounds__(256)
void wt_prep(const float* __restrict__ wq, const float* __restrict__ wk,
             const float* __restrict__ wv, const float* __restrict__ wo,
             const float* __restrict__ wg, const float* __restrict__ wu,
             const float* __restrict__ wd, int l) {
    __shared__ float t[64][65];
    int tb = blockIdx.x, tid = threadIdx.x;
    const float* src; __nv_bfloat16 *dh, *dl;
    int K, N, tloc, rowoff = 0, inter = 0;
    if (tb < 375) {
        K = DMODEL;
        dh = g_wqkv_h; dl = g_wqkv_l;
        if (tb < 225)      { src = wq + (size_t)l * DMODEL * QDIM;  N = QDIM;  tloc = tb; }
        else if (tb < 300) { src = wk + (size_t)l * DMODEL * KVDIM; N = KVDIM; tloc = tb - 225; rowoff = QDIM; }
        else               { src = wv + (size_t)l * DMODEL * KVDIM; N = KVDIM; tloc = tb - 300; rowoff = QDIM + KVDIM; }
    } else if (tb < 600) {
        src = wo + (size_t)l * QDIM * DMODEL; K = QDIM; N = DMODEL; tloc = tb - 375;
        dh = g_wo_h; dl = g_wo_l;
    } else if (tb < 1800) {
        K = DMODEL; N = FF; inter = 1;
        dh = g_wgu_h; dl = g_wgu_l;
        if (tb < 1200) { src = wg + (size_t)l * DMODEL * FF; tloc = tb - 600; }
        else           { src = wu + (size_t)l * DMODEL * FF; tloc = tb - 1200; rowoff = 8; }
    } else {
        src = wd + (size_t)l * FF * DMODEL; K = FF; N = DMODEL; tloc = tb - 1800;
        dh = g_wd_h; dl = g_wd_l;
    }
    int tiles_n = N >> 6;
    int n0 = (tloc % tiles_n) * 64, k0 = (tloc / tiles_n) * 64;

    int trr = tid >> 4, tc4 = (tid & 15) * 4;
    #pragma unroll
    for (int i = 0; i < 4; i++) {
        int r = trr + 16 * i;
        float4 v = *(const float4*)(src + (size_t)(k0 + r) * N + n0 + tc4);
        t[r][tc4] = v.x; t[r][tc4 + 1] = v.y; t[r][tc4 + 2] = v.z; t[r][tc4 + 3] = v.w;
    }
    __syncthreads();

    int kc = (tid & 7) * 8;
    #pragma unroll
    for (int half = 0; half < 2; half++) {
        int rn = (tid >> 3) + half * 32;
        __nv_bfloat16 hb[8], lb[8];
        #pragma unroll
        for (int e = 0; e < 8; e++) {
            float v = t[kc + e][rn];
            __nv_bfloat16 hh = __float2bfloat16(v);
            hb[e] = hh;
            lb[e] = __float2bfloat16(v - __bfloat162float(hh));
        }
        int n = n0 + rn;
        int row = inter ? (((n >> 3) << 4) + (n & 7) + rowoff) : (n + rowoff);
        *(uint4*)(dh + (size_t)row * K + k0 + kc) = *(uint4*)hb;
        *(uint4*)(dl + (size_t)row * K + k0 + kc) = *(uint4*)lb;
    }
}

// ---------------- RMSNorm with fused bf16 split ----------------
__global__ void rmsnorm_split(const float* __restrict__ x, const float* __restrict__ w,
                              __nv_bfloat16* __restrict__ oh, __nv_bfloat16* __restrict__ ol) {
    int row = blockIdx.x;
    const float* xr = x + (size_t)row * DMODEL;
    float ss = 0.f;
    for (int i = threadIdx.x; i < DMODEL; i += blockDim.x) {
        float v = xr[i];
        ss += v * v;
    }
    __shared__ float red[32];
    #pragma unroll
    for (int o = 16; o; o >>= 1) ss += __shfl_xor_sync(0xffffffffu, ss, o);
    int wid = threadIdx.x >> 5, lid = threadIdx.x & 31;
    if (lid == 0) red[wid] = ss;
    __syncthreads();
    if (wid == 0) {
        float v = (lid < (blockDim.x >> 5)) ? red[lid] : 0.f;
        #pragma unroll
        for (int o = 16; o; o >>= 1) v += __shfl_xor_sync(0xffffffffu, v, o);
        if (lid == 0) red[0] = rsqrtf(v / (float)DMODEL + 1e-5f);
    }
    __syncthreads();
    float inv = red[0];
    for (int i = threadIdx.x; i < DMODEL; i += blockDim.x) {
        float y = xr[i] * inv * w[i];
        __nv_bfloat16 h = __float2bfloat16(y);
        oh[(size_t)row * DMODEL + i] = h;
        ol[(size_t)row * DMODEL + i] = __float2bfloat16(y - __bfloat162float(h));
    }
}

// ---------------- rope + split + relayout for MMA attention ------
__global__ void rope_split(const float* __restrict__ qkv, const int* __restrict__ pos) {
    __shared__ float T[64][65];
    int tb = blockIdx.x, tid = threadIdx.x;
    int kind, b, hd, st, off;
    if (tb < 480)      { kind = 0; int r = tb;       b = r / (HQ * 16);  r %= HQ * 16;  hd = r / 16; st = r % 16; off = hd * DH; }
    else if (tb < 640) { kind = 1; int r = tb - 480; b = r / (HKV * 16); r %= HKV * 16; hd = r / 16; st = r % 16; off = QDIM + hd * DH; }
    else               { kind = 2; int r = tb - 640; b = r / (HKV * 16); r %= HKV * 16; hd = r / 16; st = r % 16; off = QDIM + KVDIM + hd * DH; }

    for (int u = tid; u < 1024; u += 256) {
        int r = u >> 4, c4 = (u & 15) * 4;
        float4 v = *(const float4*)(qkv + (size_t)(b * SEQ + st * 64 + r) * QKVN + off + c4);
        T[r][c4] = v.x; T[r][c4 + 1] = v.y; T[r][c4 + 2] = v.z; T[r][c4 + 3] = v.w;
    }
    __syncthreads();

    if (kind <= 1) {
        for (int u = tid; u < 2048; u += 256) {
            int r = u >> 5, d = u & 31;
            float p = (float)pos[b * SEQ + st * 64 + r];
            float ang = p * exp2f((float)d * -0.41524101186098285f);
            float sn, cs;
            sincosf(ang, &sn, &cs);
            float x1 = T[r][d], x2 = T[r][d + 32];
            T[r][d]      = x1 * cs - x2 * sn;
            T[r][d + 32] = x2 * cs + x1 * sn;
        }
        __syncthreads();
    }

    if (kind == 0) {
        __nv_bfloat16* oh = g_qh; __nv_bfloat16* ol = g_ql;
        size_t base = ((size_t)(b * HQ + hd) * SEQ + st * 64);
        for (int u = tid; u < 4096; u += 256) {
            int r = u >> 6, d = u & 63;
            float y = T[r][d] * 0.125f;
            __nv_bfloat16 h = __float2bfloat16(y);
            oh[(base + r) * DH + d] = h;
            ol[(base + r) * DH + d] = __float2bfloat16(y - __bfloat162float(h));
        }
    } else if (kind == 1) {
        size_t base = ((size_t)(b * HKV + hd) * SEQ + st * 64);
        for (int u = tid; u < 4096; u += 256) {
            int r = u >> 6, d = u & 63;
            float y = T[r][d];
            __nv_bfloat16 h = __float2bfloat16(y);
            g_kh[(base + r) * DH + d] = h;
            g_kl[(base + r) * DH + d] = __float2bfloat16(y - __bfloat162float(h));
        }
    } else {
        size_t base = (size_t)(b * HKV + hd) * DH;
        for (int u = tid; u < 4096; u += 256) {
            int d = u >> 6, r = u & 63;
            float y = T[r][d];
            __nv_bfloat16 h = __float2bfloat16(y);
            g_vth[(base + d) * SEQ + st * 64 + r] = h;
            g_vtl[(base + d) * SEQ + st * 64 + r] = __float2bfloat16(y - __bfloat162float(h));
        }
    }
}

// ---------------- MMA flash attention (causal, GQA, longest-first) ----------
#define AT_SMEM (16384 + 2*32768)   // 81920

__global__ __launch_bounds__(128, 2)
void attn_mma(const __nv_bfloat16* __restrict__ qh_, const __nv_bfloat16* __restrict__ ql_,
              const __nv_bfloat16* __restrict__ kh_, const __nv_bfloat16* __restrict__ kl_,
              const __nv_bfloat16* __restrict__ vh_, const __nv_bfloat16* __restrict__ vl_,
              __nv_bfloat16* __restrict__ oh_, __nv_bfloat16* __restrict__ ol_) {
    extern __shared__ char smc[];
    uint32_t smb = smem_u32(smc);
    int qt = (int)gridDim.x - 1 - (int)blockIdx.x;
    int bh = blockIdx.y, b = bh / HQ, hq = bh % HQ, hk = hq / (HQ / HKV);
    int tid = threadIdx.x, wid = tid >> 5, lane = tid & 31;

    int tr = tid >> 3, tj = tid & 7;
    uint32_t tsw = (uint32_t)((tj ^ (tr & 7)) << 4);
    const __nv_bfloat16* gq  = qh_ + ((size_t)(b * HQ + hq) * SEQ + qt * 64 + tr) * DH + tj * 8;
    const __nv_bfloat16* gql = ql_ + ((size_t)(b * HQ + hq) * SEQ + qt * 64 + tr) * DH + tj * 8;
    const __nv_bfloat16* gk  = kh_ + ((size_t)(b * HKV + hk) * SEQ + tr) * DH + tj * 8;
    const __nv_bfloat16* gkl = kl_ + ((size_t)(b * HKV + hk) * SEQ + tr) * DH + tj * 8;
    const __nv_bfloat16* gv  = vh_ + ((size_t)(b * HKV + hk) * DH + tr) * SEQ + tj * 8;
    const __nv_bfloat16* gvl = vl_ + ((size_t)(b * HKV + hk) * DH + tr) * SEQ + tj * 8;

    #pragma unroll
    for (int i = 0; i < 4; i++) {
        uint32_t d = smb + (uint32_t)((tr + 16 * i) * 128) + tsw;
        cpasync16(d,         gq  + (size_t)(16 * i) * DH);
        cpasync16(d + 8192u, gql + (size_t)(16 * i) * DH);
    }
    #pragma unroll
    for (int i = 0; i < 4; i++) {
        uint32_t d = smb + 16384u + (uint32_t)((tr + 16 * i) * 128) + tsw;
        cpasync16(d,          gk  + (size_t)(16 * i) * DH);
        cpasync16(d + 8192u,  gkl + (size_t)(16 * i) * DH);
        cpasync16(d + 16384u, gv  + (size_t)(16 * i) * SEQ);
        cpasync16(d + 24576u, gvl + (size_t)(16 * i) * SEQ);
    }
    CP_COMMIT();

    float o[8][4];
    #pragma unroll
    for (int nt = 0; nt < 8; nt++)
        #pragma unroll
        for (int i = 0; i < 4; i++) o[nt][i] = 0.f;
    float m_a = -1e30f, m_b = -1e30f, l_a = 0.f, l_b = 0.f;

    int sxor = lane & 7;
    uint32_t aRow = (uint32_t)((wid * 16 + (lane & 15)) * 128);
    int a_cs = lane >> 4;
    uint32_t bRow = (uint32_t)(((lane & 7) + ((lane >> 4) << 3)) * 128);
    int b_cs = (lane >> 3) & 1;

    for (int t = 0; t <= qt; t++) {
        if (t + 1 <= qt) {
            uint32_t nb = smb + 16384u + (uint32_t)(((t + 1) & 1) * 32768);
            #pragma unroll
            for (int i = 0; i < 4; i++) {
                uint32_t d = nb + (uint32_t)((tr + 16 * i) * 128) + tsw;
                cpasync16(d,          gk  + (size_t)(t + 1) * 4096 + (size_t)(16 * i) * DH);
                cpasync16(d + 8192u,  gkl + (size_t)(t + 1) * 4096 + (size_t)(16 * i) * DH);
                cpasync16(d + 16384u, gv  + (size_t)(t + 1) * 64 + (size_t)(16 * i) * SEQ);
                cpasync16(d + 24576u, gvl + (size_t)(t + 1) * 64 + (size_t)(16 * i) * SEQ);
            }
            CP_COMMIT();
            CP_WAIT1();
        } else {
            CP_WAIT0();
        }
        __syncthreads();
        uint32_t sb = smb + 16384u + (uint32_t)((t & 1) * 32768);

        float s[8][4];
        #pragma unroll
        for (int nt = 0; nt < 8; nt++)
            #pragma unroll
            for (int i = 0; i < 4; i++) s[nt][i] = 0.f;
        #pragma unroll
        for (int kk = 0; kk < 4; kk++) {
            uint32_t aa = smb + aRow + (uint32_t)(((2 * kk + a_cs) ^ sxor) << 4);
            uint32_t ah[4], al[4];
            ldm4(ah, aa);
            ldm4(al, aa + 8192u);
            #pragma unroll
            for (int np = 0; np < 4; np++) {
                uint32_t ba = sb + bRow + (uint32_t)(np * 2048) + (uint32_t)(((2 * kk + b_cs) ^ sxor) << 4);
                uint32_t kh4[4], kl4[4];
                ldm4(kh4, ba);
                ldm4(kl4, ba + 8192u);
                mma16816(s[2*np],   ah, kh4);
                mma16816(s[2*np],   ah, kl4);
                mma16816(s[2*np],   al, kh4);
                mma16816(s[2*np+1], ah, kh4 + 2);
                mma16816(s[2*np+1], ah, kl4 + 2);
                mma16816(s[2*np+1], al, kh4 + 2);
            }
        }

        if (t == qt) {
            int iA = wid * 16 + (lane >> 2);
            int jb = (lane & 3) * 2;
            #pragma unroll
            for (int nt = 0; nt < 8; nt++) {
                int j0 = nt * 8 + jb;
                if (j0     > iA)     s[nt][0] = -1e30f;
                if (j0 + 1 > iA)     s[nt][1] = -1e30f;
                if (j0     > iA + 8) s[nt][2] = -1e30f;
                if (j0 + 1 > iA + 8) s[nt][3] = -1e30f;
            }
        }

        float mA = -1e30f, mB = -1e30f;
        #pragma unroll
        for (int nt = 0; nt < 8; nt++) {
            mA = fmaxf(mA, fmaxf(s[nt][0], s[nt][1]));
            mB = fmaxf(mB, fmaxf(s[nt][2], s[nt][3]));
        }
        mA = fmaxf(mA, __shfl_xor_sync(0xffffffffu, mA, 1));
        mA = fmaxf(mA, __shfl_xor_sync(0xffffffffu, mA, 2));
        mB = fmaxf(mB, __shfl_xor_sync(0xffffffffu, mB, 1));
        mB = fmaxf(mB, __shfl_xor_sync(0xffffffffu, mB, 2));
        float mnA = fmaxf(m_a, mA), mnB = fmaxf(m_b, mB);
        float scA = __expf(m_a - mnA), scB = __expf(m_b - mnB);
        float suA = 0.f, suB = 0.f;
        #pragma unroll
        for (int nt = 0; nt < 8; nt++) {
            s[nt][0] = __expf(s[nt][0] - mnA); suA += s[nt][0];
            s[nt][1] = __expf(s[nt][1] - mnA); suA += s[nt][1];
            s[nt][2] = __expf(s[nt][2] - mnB); suB += s[nt][2];
            s[nt][3] = __expf(s[nt][3] - mnB); suB += s[nt][3];
        }
        suA += __shfl_xor_sync(0xffffffffu, suA, 1);
        suA += __shfl_xor_sync(0xffffffffu, suA, 2);
        suB += __shfl_xor_sync(0xffffffffu, suB, 1);
        suB += __shfl_xor_sync(0xffffffffu, suB, 2);
        l_a = l_a * scA + suA;
        l_b = l_b * scB + suB;
        m_a = mnA; m_b = mnB;
        #pragma unroll
        for (int nt = 0; nt < 8; nt++) {
            o[nt][0] *= scA; o[nt][1] *= scA;
            o[nt][2] *= scB; o[nt][3] *= scB;
        }

        #pragma unroll
        for (int kt = 0; kt < 4; kt++) {
            float p00 = s[2*kt][0],   p01 = s[2*kt][1],   p02 = s[2*kt][2],   p03 = s[2*kt][3];
            float p10 = s[2*kt+1][0], p11 = s[2*kt+1][1], p12 = s[2*kt+1][2], p13 = s[2*kt+1][3];
            uint32_t aPh[4], aPl[4];
            aPh[0] = packbf(p00, p01);
            aPh[1] = packbf(p02, p03);
            aPh[2] = packbf(p10, p11);
            aPh[3] = packbf(p12, p13);
            __nv_bfloat162* hp;
            hp = (__nv_bfloat162*)&aPh[0];
            aPl[0] = packbf(p00 - __bfloat162float(hp->x), p01 - __bfloat162float(hp->y));
            hp = (__nv_bfloat162*)&aPh[1];
            aPl[1] = packbf(p02 - __bfloat162float(hp->x), p03 - __bfloat162float(hp->y));
            hp = (__nv_bfloat162*)&aPh[2];
            aPl[2] = packbf(p10 - __bfloat162float(hp->x), p11 - __bfloat162float(hp->y));
            hp = (__nv_bfloat162*)&aPh[3];
            aPl[3] = packbf(p12 - __bfloat162float(hp->x), p13 - __bfloat162float(hp->y));
            #pragma unroll
            for (int np = 0; np < 4; np++) {
                uint32_t va = sb + 16384u + bRow + (uint32_t)(np * 2048) + (uint32_t)(((2 * kt + b_cs) ^ sxor) << 4);
                uint32_t vh4[4], vl4[4];
                ldm4(vh4, va);
                ldm4(vl4, va + 8192u);
                mma16816(o[2*np],   aPh, vh4);
                mma16816(o[2*np],   aPh, vl4);
                mma16816(o[2*np],   aPl, vh4);
                mma16816(o[2*np+1], aPh, vh4 + 2);
                mma16816(o[2*np+1], aPh, vl4 + 2);
                mma16816(o[2*np+1], aPl, vh4 + 2);
            }
        }
        __syncthreads();
    }

    float ivA = 1.f / l_a, ivB = 1.f / l_b;
    size_t rA = (size_t)(b * SEQ + qt * 64 + wid * 16 + (lane >> 2));
    size_t rB = rA + 8;
    int cb = hq * DH + (lane & 3) * 2;
    #pragma unroll
    for (int nt = 0; nt < 8; nt++) {
        int c = cb + nt * 8;
        float y0 = o[nt][0] * ivA, y1 = o[nt][1] * ivA;
        __nv_bfloat16 h0 = __float2bfloat16(y0), h1 = __float2bfloat16(y1);
        *(__nv_bfloat162*)(oh_ + rA * QDIM + c) = __nv_bfloat162(h0, h1);
        *(__nv_bfloat162*)(ol_ + rA * QDIM + c) = __nv_bfloat162(
            __float2bfloat16(y0 - __bfloat162float(h0)),
            __float2bfloat16(y1 - __bfloat162float(h1)));
        float y2 = o[nt][2] * ivB, y3 = o[nt][3] * ivB;
        __nv_bfloat16 h2 = __float2bfloat16(y2), h3 = __float2bfloat16(y3);
        *(__nv_bfloat162*)(oh_ + rB * QDIM + c) = __nv_bfloat162(h2, h3);
        *(__nv_bfloat162*)(ol_ + rB * QDIM + c) = __nv_bfloat162(
            __float2bfloat16(y2 - __bfloat162float(h2)),
            __float2bfloat16(y3 - __bfloat162float(h3)));
    }
}

// ---------------- host driver ----------------
extern "C" void kernel_launch(void* const* d_in, const int* in_sizes, int n_in,
                              void* d_out, int out_size) {
    (void)in_sizes; (void)n_in; (void)out_size;
    const float* prefix = (const float*)d_in[0];
    const float* ln1    = (const float*)d_in[1];
    const float* wq     = (const float*)d_in[2];
    const float* wk     = (const float*)d_in[3];
    const float* wv     = (const float*)d_in[4];
    const float* wo     = (const float*)d_in[5];
    const float* ln2    = (const float*)d_in[6];
    const float* wg     = (const float*)d_in[7];
    const float* wu     = (const float*)d_in[8];
    const float* wd     = (const float*)d_in[9];
    const int*   pos    = (const int*)d_in[11];
    float* h = (float*)d_out;

    __nv_bfloat16 *hn_h, *hn_l, *at_h, *at_l, *ac_h, *ac_l;
    __nv_bfloat16 *qh, *ql, *kh, *kl, *vth, *vtl;
    __nv_bfloat16 *wqkv_h, *wqkv_l, *wo_h, *wo_l, *wgu_h, *wgu_l, *wd_h, *wd_l;
    float *qkv;
    cudaGetSymbolAddress((void**)&hn_h, g_hn_h);
    cudaGetSymbolAddress((void**)&hn_l, g_hn_l);
    cudaGetSymbolAddress((void**)&qkv,  g_qkv);
    cudaGetSymbolAddress((void**)&at_h, g_at_h);
    cudaGetSymbolAddress((void**)&at_l, g_at_l);
    cudaGetSymbolAddress((void**)&ac_h, g_ac_h);
    cudaGetSymbolAddress((void**)&ac_l, g_ac_l);
    cudaGetSymbolAddress((void**)&qh,  g_qh);
    cudaGetSymbolAddress((void**)&ql,  g_ql);
    cudaGetSymbolAddress((void**)&kh,  g_kh);
    cudaGetSymbolAddress((void**)&kl,  g_kl);
    cudaGetSymbolAddress((void**)&vth, g_vth);
    cudaGetSymbolAddress((void**)&vtl, g_vtl);
    cudaGetSymbolAddress((void**)&wqkv_h, g_wqkv_h);
    cudaGetSymbolAddress((void**)&wqkv_l, g_wqkv_l);
    cudaGetSymbolAddress((void**)&wo_h,   g_wo_h);
    cudaGetSymbolAddress((void**)&wo_l,   g_wo_l);
    cudaGetSymbolAddress((void**)&wgu_h,  g_wgu_h);
    cudaGetSymbolAddress((void**)&wgu_l,  g_wgu_l);
    cudaGetSymbolAddress((void**)&wd_h,   g_wd_h);
    cudaGetSymbolAddress((void**)&wd_l,   g_wd_l);

    cudaFuncSetAttribute(mma_gemm<0>, cudaFuncAttributeMaxDynamicSharedMemorySize, GEMM_SMEM);
    cudaFuncSetAttribute(mma_gemm<1>, cudaFuncAttributeMaxDynamicSharedMemorySize, GEMM_SMEM);
    cudaFuncSetAttribute(mma_gemm_gu2, cudaFuncAttributeMaxDynamicSharedMemorySize, GU2_SMEM);
    cudaFuncSetAttribute(attn_mma,    cudaFuncAttributeMaxDynamicSharedMemorySize, AT_SMEM);

    cudaMemcpyAsync(h, prefix, (size_t)MROWS * DMODEL * sizeof(float),
                    cudaMemcpyDeviceToDevice, 0);

    for (int l = 0; l < NLAYERS; l++) {
        wt_prep<<<2400, 256>>>(wq, wk, wv, wo, wg, wu, wd, l);

        // attention block
        rmsnorm_split<<<MROWS, 256>>>(h, ln1 + (size_t)l * DMODEL, hn_h, hn_l);
        mma_gemm<0><<<dim3(QKVN / 64, MROWS / 128), 128, GEMM_SMEM>>>(
            hn_h, hn_l, wqkv_h, wqkv_l, qkv, QKVN, DMODEL);
        rope_split<<<800, 256>>>(qkv, pos);
        attn_mma<<<dim3(SEQ / 64, BATCH * HQ), 128, AT_SMEM>>>(
            qh, ql, kh, kl, vth, vtl, at_h, at_l);
        mma_gemm<1><<<dim3(DMODEL / 64, MROWS / 128), 128, GEMM_SMEM>>>(
            at_h, at_l, wo_h, wo_l, h, DMODEL, QDIM);

        // mlp block
        rmsnorm_split<<<MROWS, 256>>>(h, ln2 + (size_t)l * DMODEL, hn_h, hn_l);
        mma_gemm_gu2<<<dim3(2 * FF / 128, MROWS / 128), 256, GU2_SMEM>>>(
            hn_h, hn_l, wgu_h, wgu_l, ac_h, ac_l, 2 * FF, DMODEL);
        mma_gemm<1><<<dim3(DMODEL / 64, MROWS / 128), 128, GEMM_SMEM>>>(
            ac_h, ac_l, wd_h, wd_l, h, DMODEL, FF);
    }
}

// round 15
// speedup vs baseline: 1.0792x; 1.0792x over previous
#include <cuda_runtime.h>
#include <cuda_bf16.h>
#include <math.h>
#include <stdint.h>

#define NLAYERS 16
#define DMODEL 960
#define HQ 15
#define HKV 5
#define DH 64
#define FF 2560
#define BATCH 2
#define SEQ 1024
#define MROWS (BATCH*SEQ)   // 2048
#define QDIM (HQ*DH)        // 960
#define KVDIM (HKV*DH)      // 320
#define QKVN (QDIM + 2*KVDIM) // 1600

// ---------------- scratch (no allocations allowed) ----------------
__device__ __nv_bfloat16 g_hn_h[MROWS*DMODEL];
__device__ __nv_bfloat16 g_hn_l[MROWS*DMODEL];
__device__ float         g_qkv [MROWS*QKVN];
__device__ __nv_bfloat16 g_at_h[MROWS*QDIM];
__device__ __nv_bfloat16 g_at_l[MROWS*QDIM];
__device__ __nv_bfloat16 g_ac_h[MROWS*FF];
__device__ __nv_bfloat16 g_ac_l[MROWS*FF];
// attention operands (split bf16)
__device__ __nv_bfloat16 g_qh [MROWS*QDIM];
__device__ __nv_bfloat16 g_ql [MROWS*QDIM];
__device__ __nv_bfloat16 g_kh [MROWS*KVDIM];
__device__ __nv_bfloat16 g_kl [MROWS*KVDIM];
__device__ __nv_bfloat16 g_vth[MROWS*KVDIM];
__device__ __nv_bfloat16 g_vtl[MROWS*KVDIM];
// transposed split weights, PER LAYER reused buffers ([N][K] row-major bf16)
__device__ __nv_bfloat16 g_wqkv_h[QKVN*DMODEL];
__device__ __nv_bfloat16 g_wqkv_l[QKVN*DMODEL];
__device__ __nv_bfloat16 g_wo_h [DMODEL*QDIM];
__device__ __nv_bfloat16 g_wo_l [DMODEL*QDIM];
__device__ __nv_bfloat16 g_wgu_h[2*FF*DMODEL];   // gate/up 8-col interleave
__device__ __nv_bfloat16 g_wgu_l[2*FF*DMODEL];
__device__ __nv_bfloat16 g_wd_h [DMODEL*FF];
__device__ __nv_bfloat16 g_wd_l [DMODEL*FF];

// ---------------- warp-mma helpers ----------------
__device__ __forceinline__ uint32_t smem_u32(const void* p) {
    uint32_t a;
    asm("{ .reg .u64 t; cvta.to.shared.u64 t, %1; cvt.u32.u64 %0, t; }" : "=r"(a) : "l"(p));
    return a;
}
__device__ __forceinline__ void ldm4(uint32_t* r, uint32_t addr) {
    asm volatile("ldmatrix.sync.aligned.m8n8.x4.shared.b16 {%0,%1,%2,%3}, [%4];"
        : "=r"(r[0]), "=r"(r[1]), "=r"(r[2]), "=r"(r[3]) : "r"(addr));
}
__device__ __forceinline__ void mma16816(float* c, const uint32_t* a, const uint32_t* b) {
    asm volatile("mma.sync.aligned.m16n8k16.row.col.f32.bf16.bf16.f32 "
        "{%0,%1,%2,%3}, {%4,%5,%6,%7}, {%8,%9}, {%0,%1,%2,%3};"
        : "+f"(c[0]), "+f"(c[1]), "+f"(c[2]), "+f"(c[3])
        : "r"(a[0]), "r"(a[1]), "r"(a[2]), "r"(a[3]), "r"(b[0]), "r"(b[1]));
}
__device__ __forceinline__ void cpasync16(uint32_t dst, const void* src) {
    asm volatile("cp.async.cg.shared.global [%0], [%1], 16;" :: "r"(dst), "l"(src));
}
#define CP_COMMIT() asm volatile("cp.async.commit_group;" ::: "memory")
#define CP_WAIT1()  asm volatile("cp.async.wait_group 1;" ::: "memory")
#define CP_WAIT0()  asm volatile("cp.async.wait_group 0;" ::: "memory")

__device__ __forceinline__ uint32_t packbf(float a, float b) {
    __nv_bfloat162 t = __floats2bfloat162_rn(a, b);
    return *(uint32_t*)&t;
}

// ---------------- mma GEMM 128x64 (proven core) --------------
// EPI: 0 = store fp32 C, 1 = C += , 2 = fused silu(gate)*up -> split bf16
// EPI: 3 = split-K (blockIdx.z halves K) with atomicAdd into C
#define STAGE_B 49152
#define GEMM_SMEM (2*STAGE_B)   // 98304

template <int EPI>
__global__ __launch_bounds__(128, 2)
void mma_gemm(const __nv_bfloat16* __restrict__ Ah, const __nv_bfloat16* __restrict__ Al,
              const __nv_bfloat16* __restrict__ Bh, const __nv_bfloat16* __restrict__ Bl,
              float* __restrict__ C, __nv_bfloat16* __restrict__ Oh,
              __nv_bfloat16* __restrict__ Ol, int N, int K) {
    extern __shared__ __nv_bfloat16 sm[];
    uint32_t smb = smem_u32(sm);

    int tid = threadIdx.x, wid = tid >> 5, lane = tid & 31;
    int brow = blockIdx.y * 128, bcol = blockIdx.x * 64;
    int warp_m = wid >> 1, warp_n = wid & 1;

    // split-K bounds
    int nch_total = K >> 6;
    int nch = nch_total, koff = 0;
    if (EPI == 3) {
        int half0 = (nch_total + 1) >> 1;
        if (blockIdx.z == 0) { nch = half0; }
        else { nch = nch_total - half0; koff = half0 << 6; }
    }

    float acc[4][4][4];
    #pragma unroll
    for (int mt = 0; mt < 4; mt++)
        #pragma unroll
        for (int nt = 0; nt < 4; nt++)
            #pragma unroll
            for (int i = 0; i < 4; i++) acc[mt][nt][i] = 0.f;

    int tr = tid >> 3, tj = tid & 7;
    uint32_t tsw = (uint32_t)((tj ^ (tr & 7)) << 4);
    const __nv_bfloat16* gAh = Ah + (size_t)(brow + tr) * K + koff + tj * 8;
    const __nv_bfloat16* gAl = Al + (size_t)(brow + tr) * K + koff + tj * 8;
    const __nv_bfloat16* gBh = Bh + (size_t)(bcol + tr) * K + koff + tj * 8;
    const __nv_bfloat16* gBl = Bl + (size_t)(bcol + tr) * K + koff + tj * 8;

    int sxor = lane & 7;
    uint32_t aRowOff = (uint32_t)((warp_m * 64 + (lane & 15)) * 128);
    int a_cs = lane >> 4;
    uint32_t bRowOff = (uint32_t)((warp_n * 32 + (lane & 7) + ((lane >> 4) << 3)) * 128);
    int b_cs = (lane >> 3) & 1;

    {
        #pragma unroll
        for (int i = 0; i < 8; i++) {
            uint32_t d = smb + (uint32_t)((tr + 16 * i) * 128) + tsw;
            cpasync16(d,          gAh + (size_t)(16 * i) * K);
            cpasync16(d + 16384u, gAl + (size_t)(16 * i) * K);
        }
        #pragma unroll
        for (int i = 0; i < 4; i++) {
            uint32_t d = smb + 32768u + (uint32_t)((tr + 16 * i) * 128) + tsw;
            cpasync16(d,         gBh + (size_t)(16 * i) * K);
            cpasync16(d + 8192u, gBl + (size_t)(16 * i) * K);
        }
        CP_COMMIT();
    }

    for (int ch = 0; ch < nch; ch++) {
        uint32_t sbase = smb + (uint32_t)((ch & 1) ? STAGE_B : 0);
        if (ch + 1 < nch) {
            uint32_t nbase = smb + (uint32_t)(((ch + 1) & 1) ? STAGE_B : 0);
            int k0 = (ch + 1) << 6;
            #pragma unroll
            for (int i = 0; i < 8; i++) {
                uint32_t d = nbase + (uint32_t)((tr + 16 * i) * 128) + tsw;
                cpasync16(d,          gAh + (size_t)(16 * i) * K + k0);
                cpasync16(d + 16384u, gAl + (size_t)(16 * i) * K + k0);
            }
            #pragma unroll
            for (int i = 0; i < 4; i++) {
                uint32_t d = nbase + 32768u + (uint32_t)((tr + 16 * i) * 128) + tsw;
                cpasync16(d,         gBh + (size_t)(16 * i) * K + k0);
                cpasync16(d + 8192u, gBl + (size_t)(16 * i) * K + k0);
            }
            CP_COMMIT();
            CP_WAIT1();
        } else {
            CP_WAIT0();
        }
        __syncthreads();

        #pragma unroll
        for (int kk = 0; kk < 4; kk++) {
            uint32_t bCh = (uint32_t)((((kk * 2 + b_cs) ^ sxor)) << 4);
            uint32_t bAddr = sbase + 32768u + bRowOff + bCh;
            uint32_t bh[8], bl[8];
            ldm4(bh,     bAddr);
            ldm4(bh + 4, bAddr + 2048u);
            ldm4(bl,     bAddr + 8192u);
            ldm4(bl + 4, bAddr + 10240u);
            uint32_t aCh = (uint32_t)((((kk * 2 + a_cs) ^ sxor)) << 4);
            #pragma unroll
            for (int mt = 0; mt < 4; mt++) {
                uint32_t aAddr = sbase + aRowOff + (uint32_t)(mt * 2048) + aCh;
                uint32_t ah[4], al[4];
                ldm4(ah, aAddr);
                ldm4(al, aAddr + 16384u);
                #pragma unroll
                for (int nt = 0; nt < 4; nt++) {
                    mma16816(acc[mt][nt], ah, bh + 2 * nt);
                    mma16816(acc[mt][nt], ah, bl + 2 * nt);
                    mma16816(acc[mt][nt], al, bh + 2 * nt);
                }
            }
        }
        __syncthreads();
    }

    if (EPI == 2) {
        int NOUT = N >> 1;
        #pragma unroll
        for (int mt = 0; mt < 4; mt++) {
            int r0 = brow + warp_m * 64 + mt * 16 + (lane >> 2);
            #pragma unroll
            for (int j = 0; j < 2; j++) {
                int fcol = (bcol >> 1) + warp_n * 16 + j * 8 + (lane & 3) * 2;
                #pragma unroll
                for (int half = 0; half < 2; half++) {
                    int r = r0 + half * 8;
                    float g0 = acc[mt][2*j][half * 2 + 0], u0 = acc[mt][2*j+1][half * 2 + 0];
                    float g1 = acc[mt][2*j][half * 2 + 1], u1 = acc[mt][2*j+1][half * 2 + 1];
                    float y0 = (g0 / (1.f + __expf(-g0))) * u0;
                    float y1 = (g1 / (1.f + __expf(-g1))) * u1;
                    __nv_bfloat16 h0 = __float2bfloat16(y0), h1 = __float2bfloat16(y1);
                    __nv_bfloat16 l0 = __float2bfloat16(y0 - __bfloat162float(h0));
                    __nv_bfloat16 l1 = __float2bfloat16(y1 - __bfloat162float(h1));
                    *(__nv_bfloat162*)(Oh + (size_t)r * NOUT + fcol) = __nv_bfloat162(h0, h1);
                    *(__nv_bfloat162*)(Ol + (size_t)r * NOUT + fcol) = __nv_bfloat162(l0, l1);
                }
            }
        }
    } else {
        #pragma unroll
        for (int mt = 0; mt < 4; mt++) {
            int r0 = brow + warp_m * 64 + mt * 16 + (lane >> 2);
            #pragma unroll
            for (int nt = 0; nt < 4; nt++) {
                int c0 = bcol + warp_n * 32 + nt * 8 + (lane & 3) * 2;
                float* p0 = C + (size_t)r0 * N + c0;
                float* p1 = p0 + 8 * (size_t)N;
                if (EPI == 3) {
                    atomicAdd(p0,     acc[mt][nt][0]);
                    atomicAdd(p0 + 1, acc[mt][nt][1]);
                    atomicAdd(p1,     acc[mt][nt][2]);
                    atomicAdd(p1 + 1, acc[mt][nt][3]);
                } else if (EPI == 1) {
                    p0[0] += acc[mt][nt][0]; p0[1] += acc[mt][nt][1];
                    p1[0] += acc[mt][nt][2]; p1[1] += acc[mt][nt][3];
                } else {
                    *(float2*)p0 = make_float2(acc[mt][nt][0], acc[mt][nt][1]);
                    *(float2*)p1 = make_float2(acc[mt][nt][2], acc[mt][nt][3]);
                }
            }
        }
    }
}

// ---------------- per-layer weight prep: 64x64 tiles, wide I/O ----------
__global__ __launch_bounds__(256)
void wt_prep(const float* __restrict__ wq, const float* __restrict__ wk,
             const float* __restrict__ wv, const float* __restrict__ wo,
             const float* __restrict__ wg, const float* __restrict__ wu,
             const float* __restrict__ wd, int l) {
    __shared__ float t[64][65];
    int tb = blockIdx.x, tid = threadIdx.x;
    const float* src; __nv_bfloat16 *dh, *dl;
    int K, N, tloc, rowoff = 0, inter = 0;
    if (tb < 375) {
        K = DMODEL;
        dh = g_wqkv_h; dl = g_wqkv_l;
        if (tb < 225)      { src = wq + (size_t)l * DMODEL * QDIM;  N = QDIM;  tloc = tb; }
        else if (tb < 300) { src = wk + (size_t)l * DMODEL * KVDIM; N = KVDIM; tloc = tb - 225; rowoff = QDIM; }
        else               { src = wv + (size_t)l * DMODEL * KVDIM; N = KVDIM; tloc = tb - 300; rowoff = QDIM + KVDIM; }
    } else if (tb < 600) {
        src = wo + (size_t)l * QDIM * DMODEL; K = QDIM; N = DMODEL; tloc = tb - 375;
        dh = g_wo_h; dl = g_wo_l;
    } else if (tb < 1800) {
        K = DMODEL; N = FF; inter = 1;
        dh = g_wgu_h; dl = g_wgu_l;
        if (tb < 1200) { src = wg + (size_t)l * DMODEL * FF; tloc = tb - 600; }
        else           { src = wu + (size_t)l * DMODEL * FF; tloc = tb - 1200; rowoff = 8; }
    } else {
        src = wd + (size_t)l * FF * DMODEL; K = FF; N = DMODEL; tloc = tb - 1800;
        dh = g_wd_h; dl = g_wd_l;
    }
    int tiles_n = N >> 6;
    int n0 = (tloc % tiles_n) * 64, k0 = (tloc / tiles_n) * 64;

    int trr = tid >> 4, tc4 = (tid & 15) * 4;
    #pragma unroll
    for (int i = 0; i < 4; i++) {
        int r = trr + 16 * i;
        float4 v = *(const float4*)(src + (size_t)(k0 + r) * N + n0 + tc4);
        t[r][tc4] = v.x; t[r][tc4 + 1] = v.y; t[r][tc4 + 2] = v.z; t[r][tc4 + 3] = v.w;
    }
    __syncthreads();

    int kc = (tid & 7) * 8;
    #pragma unroll
    for (int half = 0; half < 2; half++) {
        int rn = (tid >> 3) + half * 32;
        __nv_bfloat16 hb[8], lb[8];
        #pragma unroll
        for (int e = 0; e < 8; e++) {
            float v = t[kc + e][rn];
            __nv_bfloat16 hh = __float2bfloat16(v);
            hb[e] = hh;
            lb[e] = __float2bfloat16(v - __bfloat162float(hh));
        }
        int n = n0 + rn;
        int row = inter ? (((n >> 3) << 4) + (n & 7) + rowoff) : (n + rowoff);
        *(uint4*)(dh + (size_t)row * K + k0 + kc) = *(uint4*)hb;
        *(uint4*)(dl + (size_t)row * K + k0 + kc) = *(uint4*)lb;
    }
}

// ---------------- RMSNorm with fused bf16 split ----------------
__global__ void rmsnorm_split(const float* __restrict__ x, const float* __restrict__ w,
                              __nv_bfloat16* __restrict__ oh, __nv_bfloat16* __restrict__ ol) {
    int row = blockIdx.x;
    const float* xr = x + (size_t)row * DMODEL;
    float ss = 0.f;
    for (int i = threadIdx.x; i < DMODEL; i += blockDim.x) {
        float v = xr[i];
        ss += v * v;
    }
    __shared__ float red[32];
    #pragma unroll
    for (int o = 16; o; o >>= 1) ss += __shfl_xor_sync(0xffffffffu, ss, o);
    int wid = threadIdx.x >> 5, lid = threadIdx.x & 31;
    if (lid == 0) red[wid] = ss;
    __syncthreads();
    if (wid == 0) {
        float v = (lid < (blockDim.x >> 5)) ? red[lid] : 0.f;
        #pragma unroll
        for (int o = 16; o; o >>= 1) v += __shfl_xor_sync(0xffffffffu, v, o);
        if (lid == 0) red[0] = rsqrtf(v / (float)DMODEL + 1e-5f);
    }
    __syncthreads();
    float inv = red[0];
    for (int i = threadIdx.x; i < DMODEL; i += blockDim.x) {
        float y = xr[i] * inv * w[i];
        __nv_bfloat16 h = __float2bfloat16(y);
        oh[(size_t)row * DMODEL + i] = h;
        ol[(size_t)row * DMODEL + i] = __float2bfloat16(y - __bfloat162float(h));
    }
}

// ---------------- rope + split + relayout for MMA attention ------
__global__ void rope_split(const float* __restrict__ qkv, const int* __restrict__ pos) {
    __shared__ float T[64][65];
    int tb = blockIdx.x, tid = threadIdx.x;
    int kind, b, hd, st, off;
    if (tb < 480)      { kind = 0; int r = tb;       b = r / (HQ * 16);  r %= HQ * 16;  hd = r / 16; st = r % 16; off = hd * DH; }
    else if (tb < 640) { kind = 1; int r = tb - 480; b = r / (HKV * 16); r %= HKV * 16; hd = r / 16; st = r % 16; off = QDIM + hd * DH; }
    else               { kind = 2; int r = tb - 640; b = r / (HKV * 16); r %= HKV * 16; hd = r / 16; st = r % 16; off = QDIM + KVDIM + hd * DH; }

    for (int u = tid; u < 1024; u += 256) {
        int r = u >> 4, c4 = (u & 15) * 4;
        float4 v = *(const float4*)(qkv + (size_t)(b * SEQ + st * 64 + r) * QKVN + off + c4);
        T[r][c4] = v.x; T[r][c4 + 1] = v.y; T[r][c4 + 2] = v.z; T[r][c4 + 3] = v.w;
    }
    __syncthreads();

    if (kind <= 1) {
        for (int u = tid; u < 2048; u += 256) {
            int r = u >> 5, d = u & 31;
            float p = (float)pos[b * SEQ + st * 64 + r];
            float ang = p * exp2f((float)d * -0.41524101186098285f);
            float sn, cs;
            sincosf(ang, &sn, &cs);
            float x1 = T[r][d], x2 = T[r][d + 32];
            T[r][d]      = x1 * cs - x2 * sn;
            T[r][d + 32] = x2 * cs + x1 * sn;
        }
        __syncthreads();
    }

    if (kind == 0) {
        __nv_bfloat16* oh = g_qh; __nv_bfloat16* ol = g_ql;
        size_t base = ((size_t)(b * HQ + hd) * SEQ + st * 64);
        for (int u = tid; u < 4096; u += 256) {
            int r = u >> 6, d = u & 63;
            float y = T[r][d] * 0.125f;
            __nv_bfloat16 h = __float2bfloat16(y);
            oh[(base + r) * DH + d] = h;
            ol[(base + r) * DH + d] = __float2bfloat16(y - __bfloat162float(h));
        }
    } else if (kind == 1) {
        size_t base = ((size_t)(b * HKV + hd) * SEQ + st * 64);
        for (int u = tid; u < 4096; u += 256) {
            int r = u >> 6, d = u & 63;
            float y = T[r][d];
            __nv_bfloat16 h = __float2bfloat16(y);
            g_kh[(base + r) * DH + d] = h;
            g_kl[(base + r) * DH + d] = __float2bfloat16(y - __bfloat162float(h));
        }
    } else {
        size_t base = (size_t)(b * HKV + hd) * DH;
        for (int u = tid; u < 4096; u += 256) {
            int d = u >> 6, r = u & 63;
            float y = T[r][d];
            __nv_bfloat16 h = __float2bfloat16(y);
            g_vth[(base + d) * SEQ + st * 64 + r] = h;
            g_vtl[(base + d) * SEQ + st * 64 + r] = __float2bfloat16(y - __bfloat162float(h));
        }
    }
}

// ---------------- MMA flash attention (causal, GQA, longest-first) ----------
#define AT_SMEM (16384 + 2*32768)   // 81920

__global__ __launch_bounds__(128, 2)
void attn_mma(const __nv_bfloat16* __restrict__ qh_, const __nv_bfloat16* __restrict__ ql_,
              const __nv_bfloat16* __restrict__ kh_, const __nv_bfloat16* __restrict__ kl_,
              const __nv_bfloat16* __restrict__ vh_, const __nv_bfloat16* __restrict__ vl_,
              __nv_bfloat16* __restrict__ oh_, __nv_bfloat16* __restrict__ ol_) {
    extern __shared__ char smc[];
    uint32_t smb = smem_u32(smc);
    int qt = (int)gridDim.x - 1 - (int)blockIdx.x;
    int bh = blockIdx.y, b = bh / HQ, hq = bh % HQ, hk = hq / (HQ / HKV);
    int tid = threadIdx.x, wid = tid >> 5, lane = tid & 31;

    int tr = tid >> 3, tj = tid & 7;
    uint32_t tsw = (uint32_t)((tj ^ (tr & 7)) << 4);
    const __nv_bfloat16* gq  = qh_ + ((size_t)(b * HQ + hq) * SEQ + qt * 64 + tr) * DH + tj * 8;
    const __nv_bfloat16* gql = ql_ + ((size_t)(b * HQ + hq) * SEQ + qt * 64 + tr) * DH + tj * 8;
    const __nv_bfloat16* gk  = kh_ + ((size_t)(b * HKV + hk) * SEQ + tr) * DH + tj * 8;
    const __nv_bfloat16* gkl = kl_ + ((size_t)(b * HKV + hk) * SEQ + tr) * DH + tj * 8;
    const __nv_bfloat16* gv  = vh_ + ((size_t)(b * HKV + hk) * DH + tr) * SEQ + tj * 8;
    const __nv_bfloat16* gvl = vl_ + ((size_t)(b * HKV + hk) * DH + tr) * SEQ + tj * 8;

    #pragma unroll
    for (int i = 0; i < 4; i++) {
        uint32_t d = smb + (uint32_t)((tr + 16 * i) * 128) + tsw;
        cpasync16(d,         gq  + (size_t)(16 * i) * DH);
        cpasync16(d + 8192u, gql + (size_t)(16 * i) * DH);
    }
    #pragma unroll
    for (int i = 0; i < 4; i++) {
        uint32_t d = smb + 16384u + (uint32_t)((tr + 16 * i) * 128) + tsw;
        cpasync16(d,          gk  + (size_t)(16 * i) * DH);
        cpasync16(d + 8192u,  gkl + (size_t)(16 * i) * DH);
        cpasync16(d + 16384u, gv  + (size_t)(16 * i) * SEQ);
        cpasync16(d + 24576u, gvl + (size_t)(16 * i) * SEQ);
    }
    CP_COMMIT();

    float o[8][4];
    #pragma unroll
    for (int nt = 0; nt < 8; nt++)
        #pragma unroll
        for (int i = 0; i < 4; i++) o[nt][i] = 0.f;
    float m_a = -1e30f, m_b = -1e30f, l_a = 0.f, l_b = 0.f;

    int sxor = lane & 7;
    uint32_t aRow = (uint32_t)((wid * 16 + (lane & 15)) * 128);
    int a_cs = lane >> 4;
    uint32_t bRow = (uint32_t)(((lane & 7) + ((lane >> 4) << 3)) * 128);
    int b_cs = (lane >> 3) & 1;

    for (int t = 0; t <= qt; t++) {
        if (t + 1 <= qt) {
            uint32_t nb = smb + 16384u + (uint32_t)(((t + 1) & 1) * 32768);
            #pragma unroll
            for (int i = 0; i < 4; i++) {
                uint32_t d = nb + (uint32_t)((tr + 16 * i) * 128) + tsw;
                cpasync16(d,          gk  + (size_t)(t + 1) * 4096 + (size_t)(16 * i) * DH);
                cpasync16(d + 8192u,  gkl + (size_t)(t + 1) * 4096 + (size_t)(16 * i) * DH);
                cpasync16(d + 16384u, gv  + (size_t)(t + 1) * 64 + (size_t)(16 * i) * SEQ);
                cpasync16(d + 24576u, gvl + (size_t)(t + 1) * 64 + (size_t)(16 * i) * SEQ);
            }
            CP_COMMIT();
            CP_WAIT1();
        } else {
            CP_WAIT0();
        }
        __syncthreads();
        uint32_t sb = smb + 16384u + (uint32_t)((t & 1) * 32768);

        float s[8][4];
        #pragma unroll
        for (int nt = 0; nt < 8; nt++)
            #pragma unroll
            for (int i = 0; i < 4; i++) s[nt][i] = 0.f;
        #pragma unroll
        for (int kk = 0; kk < 4; kk++) {
            uint32_t aa = smb + aRow + (uint32_t)(((2 * kk + a_cs) ^ sxor) << 4);
            uint32_t ah[4], al[4];
            ldm4(ah, aa);
            ldm4(al, aa + 8192u);
            #pragma unroll
            for (int np = 0; np < 4; np++) {
                uint32_t ba = sb + bRow + (uint32_t)(np * 2048) + (uint32_t)(((2 * kk + b_cs) ^ sxor) << 4);
                uint32_t kh4[4], kl4[4];
                ldm4(kh4, ba);
                ldm4(kl4, ba + 8192u);
                mma16816(s[2*np],   ah, kh4);
                mma16816(s[2*np],   ah, kl4);
                mma16816(s[2*np],   al, kh4);
                mma16816(s[2*np+1], ah, kh4 + 2);
                mma16816(s[2*np+1], ah, kl4 + 2);
                mma16816(s[2*np+1], al, kh4 + 2);
            }
        }

        if (t == qt) {
            int iA = wid * 16 + (lane >> 2);
            int jb = (lane & 3) * 2;
            #pragma unroll
            for (int nt = 0; nt < 8; nt++) {
                int j0 = nt * 8 + jb;
                if (j0     > iA)     s[nt][0] = -1e30f;
                if (j0 + 1 > iA)     s[nt][1] = -1e30f;
                if (j0     > iA + 8) s[nt][2] = -1e30f;
                if (j0 + 1 > iA + 8) s[nt][3] = -1e30f;
            }
        }

        float mA = -1e30f, mB = -1e30f;
        #pragma unroll
        for (int nt = 0; nt < 8; nt++) {
            mA = fmaxf(mA, fmaxf(s[nt][0], s[nt][1]));
            mB = fmaxf(mB, fmaxf(s[nt][2], s[nt][3]));
        }
        mA = fmaxf(mA, __shfl_xor_sync(0xffffffffu, mA, 1));
        mA = fmaxf(mA, __shfl_xor_sync(0xffffffffu, mA, 2));
        mB = fmaxf(mB, __shfl_xor_sync(0xffffffffu, mB, 1));
        mB = fmaxf(mB, __shfl_xor_sync(0xffffffffu, mB, 2));
        float mnA = fmaxf(m_a, mA), mnB = fmaxf(m_b, mB);
        float scA = __expf(m_a - mnA), scB = __expf(m_b - mnB);
        float suA = 0.f, suB = 0.f;
        #pragma unroll
        for (int nt = 0; nt < 8; nt++) {
            s[nt][0] = __expf(s[nt][0] - mnA); suA += s[nt][0];
            s[nt][1] = __expf(s[nt][1] - mnA); suA += s[nt][1];
            s[nt][2] = __expf(s[nt][2] - mnB); suB += s[nt][2];
            s[nt][3] = __expf(s[nt][3] - mnB); suB += s[nt][3];
        }
        suA += __shfl_xor_sync(0xffffffffu, suA, 1);
        suA += __shfl_xor_sync(0xffffffffu, suA, 2);
        suB += __shfl_xor_sync(0xffffffffu, suB, 1);
        suB += __shfl_xor_sync(0xffffffffu, suB, 2);
        l_a = l_a * scA + suA;
        l_b = l_b * scB + suB;
        m_a = mnA; m_b = mnB;
        #pragma unroll
        for (int nt = 0; nt < 8; nt++) {
            o[nt][0] *= scA; o[nt][1] *= scA;
            o[nt][2] *= scB; o[nt][3] *= scB;
        }

        #pragma unroll
        for (int kt = 0; kt < 4; kt++) {
            float p00 = s[2*kt][0],   p01 = s[2*kt][1],   p02 = s[2*kt][2],   p03 = s[2*kt][3];
            float p10 = s[2*kt+1][0], p11 = s[2*kt+1][1], p12 = s[2*kt+1][2], p13 = s[2*kt+1][3];
            uint32_t aPh[4], aPl[4];
            aPh[0] = packbf(p00, p01);
            aPh[1] = packbf(p02, p03);
            aPh[2] = packbf(p10, p11);
            aPh[3] = packbf(p12, p13);
            __nv_bfloat162* hp;
            hp = (__nv_bfloat162*)&aPh[0];
            aPl[0] = packbf(p00 - __bfloat162float(hp->x), p01 - __bfloat162float(hp->y));
            hp = (__nv_bfloat162*)&aPh[1];
            aPl[1] = packbf(p02 - __bfloat162float(hp->x), p03 - __bfloat162float(hp->y));
            hp = (__nv_bfloat162*)&aPh[2];
            aPl[2] = packbf(p10 - __bfloat162float(hp->x), p11 - __bfloat162float(hp->y));
            hp = (__nv_bfloat162*)&aPh[3];
            aPl[3] = packbf(p12 - __bfloat162float(hp->x), p13 - __bfloat162float(hp->y));
            #pragma unroll
            for (int np = 0; np < 4; np++) {
                uint32_t va = sb + 16384u + bRow + (uint32_t)(np * 2048) + (uint32_t)(((2 * kt + b_cs) ^ sxor) << 4);
                uint32_t vh4[4], vl4[4];
                ldm4(vh4, va);
                ldm4(vl4, va + 8192u);
                mma16816(o[2*np],   aPh, vh4);
                mma16816(o[2*np],   aPh, vl4);
                mma16816(o[2*np],   aPl, vh4);
                mma16816(o[2*np+1], aPh, vh4 + 2);
                mma16816(o[2*np+1], aPh, vl4 + 2);
                mma16816(o[2*np+1], aPl, vh4 + 2);
            }
        }
        __syncthreads();
    }

    float ivA = 1.f / l_a, ivB = 1.f / l_b;
    size_t rA = (size_t)(b * SEQ + qt * 64 + wid * 16 + (lane >> 2));
    size_t rB = rA + 8;
    int cb = hq * DH + (lane & 3) * 2;
    #pragma unroll
    for (int nt = 0; nt < 8; nt++) {
        int c = cb + nt * 8;
        float y0 = o[nt][0] * ivA, y1 = o[nt][1] * ivA;
        __nv_bfloat16 h0 = __float2bfloat16(y0), h1 = __float2bfloat16(y1);
        *(__nv_bfloat162*)(oh_ + rA * QDIM + c) = __nv_bfloat162(h0, h1);
        *(__nv_bfloat162*)(ol_ + rA * QDIM + c) = __nv_bfloat162(
            __float2bfloat16(y0 - __bfloat162float(h0)),
            __float2bfloat16(y1 - __bfloat162float(h1)));
        float y2 = o[nt][2] * ivB, y3 = o[nt][3] * ivB;
        __nv_bfloat16 h2 = __float2bfloat16(y2), h3 = __float2bfloat16(y3);
        *(__nv_bfloat162*)(oh_ + rB * QDIM + c) = __nv_bfloat162(h2, h3);
        *(__nv_bfloat162*)(ol_ + rB * QDIM + c) = __nv_bfloat162(
            __float2bfloat16(y2 - __bfloat162float(h2)),
            __float2bfloat16(y3 - __bfloat162float(h3)));
    }
}

// ---------------- host driver ----------------
extern "C" void kernel_launch(void* const* d_in, const int* in_sizes, int n_in,
                              void* d_out, int out_size) {
    (void)in_sizes; (void)n_in; (void)out_size;
    const float* prefix = (const float*)d_in[0];
    const float* ln1    = (const float*)d_in[1];
    const float* wq     = (const float*)d_in[2];
    const float* wk     = (const float*)d_in[3];
    const float* wv     = (const float*)d_in[4];
    const float* wo     = (const float*)d_in[5];
    const float* ln2    = (const float*)d_in[6];
    const float* wg     = (const float*)d_in[7];
    const float* wu     = (const float*)d_in[8];
    const float* wd     = (const float*)d_in[9];
    const int*   pos    = (const int*)d_in[11];
    float* h = (float*)d_out;

    __nv_bfloat16 *hn_h, *hn_l, *at_h, *at_l, *ac_h, *ac_l;
    __nv_bfloat16 *qh, *ql, *kh, *kl, *vth, *vtl;
    __nv_bfloat16 *wqkv_h, *wqkv_l, *wo_h, *wo_l, *wgu_h, *wgu_l, *wd_h, *wd_l;
    float *qkv;
    cudaGetSymbolAddress((void**)&hn_h, g_hn_h);
    cudaGetSymbolAddress((void**)&hn_l, g_hn_l);
    cudaGetSymbolAddress((void**)&qkv,  g_qkv);
    cudaGetSymbolAddress((void**)&at_h, g_at_h);
    cudaGetSymbolAddress((void**)&at_l, g_at_l);
    cudaGetSymbolAddress((void**)&ac_h, g_ac_h);
    cudaGetSymbolAddress((void**)&ac_l, g_ac_l);
    cudaGetSymbolAddress((void**)&qh,  g_qh);
    cudaGetSymbolAddress((void**)&ql,  g_ql);
    cudaGetSymbolAddress((void**)&kh,  g_kh);
    cudaGetSymbolAddress((void**)&kl,  g_kl);
    cudaGetSymbolAddress((void**)&vth, g_vth);
    cudaGetSymbolAddress((void**)&vtl, g_vtl);
    cudaGetSymbolAddress((void**)&wqkv_h, g_wqkv_h);
    cudaGetSymbolAddress((void**)&wqkv_l, g_wqkv_l);
    cudaGetSymbolAddress((void**)&wo_h,   g_wo_h);
    cudaGetSymbolAddress((void**)&wo_l,   g_wo_l);
    cudaGetSymbolAddress((void**)&wgu_h,  g_wgu_h);
    cudaGetSymbolAddress((void**)&wgu_l,  g_wgu_l);
    cudaGetSymbolAddress((void**)&wd_h,   g_wd_h);
    cudaGetSymbolAddress((void**)&wd_l,   g_wd_l);

    cudaFuncSetAttribute(mma_gemm<0>, cudaFuncAttributeMaxDynamicSharedMemorySize, GEMM_SMEM);
    cudaFuncSetAttribute(mma_gemm<2>, cudaFuncAttributeMaxDynamicSharedMemorySize, GEMM_SMEM);
    cudaFuncSetAttribute(mma_gemm<3>, cudaFuncAttributeMaxDynamicSharedMemorySize, GEMM_SMEM);
    cudaFuncSetAttribute(attn_mma,    cudaFuncAttributeMaxDynamicSharedMemorySize, AT_SMEM);

    cudaMemcpyAsync(h, prefix, (size_t)MROWS * DMODEL * sizeof(float),
                    cudaMemcpyDeviceToDevice, 0);

    for (int l = 0; l < NLAYERS; l++) {
        wt_prep<<<2400, 256>>>(wq, wk, wv, wo, wg, wu, wd, l);

        // attention block
        rmsnorm_split<<<MROWS, 256>>>(h, ln1 + (size_t)l * DMODEL, hn_h, hn_l);
        mma_gemm<0><<<dim3(QKVN / 64, MROWS / 128), 128, GEMM_SMEM>>>(
            hn_h, hn_l, wqkv_h, wqkv_l, qkv, nullptr, nullptr, QKVN, DMODEL);
        rope_split<<<800, 256>>>(qkv, pos);
        attn_mma<<<dim3(SEQ / 64, BATCH * HQ), 128, AT_SMEM>>>(
            qh, ql, kh, kl, vth, vtl, at_h, at_l);
        mma_gemm<3><<<dim3(DMODEL / 64, MROWS / 128, 2), 128, GEMM_SMEM>>>(
            at_h, at_l, wo_h, wo_l, h, nullptr, nullptr, DMODEL, QDIM);

        // mlp block
        rmsnorm_split<<<MROWS, 256>>>(h, ln2 + (size_t)l * DMODEL, hn_h, hn_l);
        mma_gemm<2><<<dim3(2 * FF / 64, MROWS / 128), 128, GEMM_SMEM>>>(
            hn_h, hn_l, wgu_h, wgu_l, nullptr, ac_h, ac_l, 2 * FF, DMODEL);
        mma_gemm<3><<<dim3(DMODEL / 64, MROWS / 128, 2), 128, GEMM_SMEM>>>(
            ac_h, ac_l, wd_h, wd_l, h, nullptr, nullptr, DMODEL, FF);
    }
}

// round 17
// speedup vs baseline: 1.0835x; 1.0040x over previous
#include <cuda_runtime.h>
#include <cuda_bf16.h>
#include <math.h>
#include <stdint.h>

#define NLAYERS 16
#define DMODEL 960
#define HQ 15
#define HKV 5
#define DH 64
#define FF 2560
#define BATCH 2
#define SEQ 1024
#define MROWS (BATCH*SEQ)   // 2048
#define QDIM (HQ*DH)        // 960
#define KVDIM (HKV*DH)      // 320
#define QKVN (QDIM + 2*KVDIM) // 1600

// ---------------- scratch (no allocations allowed) ----------------
__device__ __nv_bfloat16 g_hn_h[MROWS*DMODEL];
__device__ __nv_bfloat16 g_hn_l[MROWS*DMODEL];
__device__ float         g_qkv [MROWS*QKVN];
__device__ __nv_bfloat16 g_at_h[MROWS*QDIM];
__device__ __nv_bfloat16 g_at_l[MROWS*QDIM];
__device__ __nv_bfloat16 g_ac_h[MROWS*FF];
__device__ __nv_bfloat16 g_ac_l[MROWS*FF];
// attention operands (split bf16)
__device__ __nv_bfloat16 g_qh [MROWS*QDIM];
__device__ __nv_bfloat16 g_ql [MROWS*QDIM];
__device__ __nv_bfloat16 g_kh [MROWS*KVDIM];
__device__ __nv_bfloat16 g_kl [MROWS*KVDIM];
__device__ __nv_bfloat16 g_vth[MROWS*KVDIM];
__device__ __nv_bfloat16 g_vtl[MROWS*KVDIM];
// transposed split weights, DOUBLE-BUFFERED by layer parity ([N][K] bf16)
__device__ __nv_bfloat16 g_wqkv_h[2*QKVN*DMODEL];
__device__ __nv_bfloat16 g_wqkv_l[2*QKVN*DMODEL];
__device__ __nv_bfloat16 g_wo_h [2*DMODEL*QDIM];
__device__ __nv_bfloat16 g_wo_l [2*DMODEL*QDIM];
__device__ __nv_bfloat16 g_wgu_h[2*2*FF*DMODEL];   // gate/up 8-col interleave
__device__ __nv_bfloat16 g_wgu_l[2*2*FF*DMODEL];
__device__ __nv_bfloat16 g_wd_h [2*DMODEL*FF];
__device__ __nv_bfloat16 g_wd_l [2*DMODEL*FF];

// ---------------- warp-mma helpers ----------------
__device__ __forceinline__ uint32_t smem_u32(const void* p) {
    uint32_t a;
    asm("{ .reg .u64 t; cvta.to.shared.u64 t, %1; cvt.u32.u64 %0, t; }" : "=r"(a) : "l"(p));
    return a;
}
__device__ __forceinline__ void ldm4(uint32_t* r, uint32_t addr) {
    asm volatile("ldmatrix.sync.aligned.m8n8.x4.shared.b16 {%0,%1,%2,%3}, [%4];"
        : "=r"(r[0]), "=r"(r[1]), "=r"(r[2]), "=r"(r[3]) : "r"(addr));
}
__device__ __forceinline__ void mma16816(float* c, const uint32_t* a, const uint32_t* b) {
    asm volatile("mma.sync.aligned.m16n8k16.row.col.f32.bf16.bf16.f32 "
        "{%0,%1,%2,%3}, {%4,%5,%6,%7}, {%8,%9}, {%0,%1,%2,%3};"
        : "+f"(c[0]), "+f"(c[1]), "+f"(c[2]), "+f"(c[3])
        : "r"(a[0]), "r"(a[1]), "r"(a[2]), "r"(a[3]), "r"(b[0]), "r"(b[1]));
}
__device__ __forceinline__ void cpasync16(uint32_t dst, const void* src) {
    asm volatile("cp.async.cg.shared.global [%0], [%1], 16;" :: "r"(dst), "l"(src));
}
#define CP_COMMIT() asm volatile("cp.async.commit_group;" ::: "memory")
#define CP_WAIT1()  asm volatile("cp.async.wait_group 1;" ::: "memory")
#define CP_WAIT0()  asm volatile("cp.async.wait_group 0;" ::: "memory")

__device__ __forceinline__ uint32_t packbf(float a, float b) {
    __nv_bfloat162 t = __floats2bfloat162_rn(a, b);
    return *(uint32_t*)&t;
}

// ---------------- mma GEMM 128x64 (proven core) --------------
// EPI: 0 = store fp32 C, 1 = C += , 2 = fused silu(gate)*up -> split bf16
// EPI: 3 = split-K (blockIdx.z halves K) with atomicAdd into C
#define STAGE_B 49152
#define GEMM_SMEM (2*STAGE_B)   // 98304

template <int EPI>
__global__ __launch_bounds__(128, 2)
void mma_gemm(const __nv_bfloat16* __restrict__ Ah, const __nv_bfloat16* __restrict__ Al,
              const __nv_bfloat16* __restrict__ Bh, const __nv_bfloat16* __restrict__ Bl,
              float* __restrict__ C, __nv_bfloat16* __restrict__ Oh,
              __nv_bfloat16* __restrict__ Ol, int N, int K) {
    extern __shared__ __nv_bfloat16 sm[];
    uint32_t smb = smem_u32(sm);

    int tid = threadIdx.x, wid = tid >> 5, lane = tid & 31;
    int brow = blockIdx.y * 128, bcol = blockIdx.x * 64;
    int warp_m = wid >> 1, warp_n = wid & 1;

    // split-K bounds
    int nch_total = K >> 6;
    int nch = nch_total, koff = 0;
    if (EPI == 3) {
        int half0 = (nch_total + 1) >> 1;
        if (blockIdx.z == 0) { nch = half0; }
        else { nch = nch_total - half0; koff = half0 << 6; }
    }

    float acc[4][4][4];
    #pragma unroll
    for (int mt = 0; mt < 4; mt++)
        #pragma unroll
        for (int nt = 0; nt < 4; nt++)
            #pragma unroll
            for (int i = 0; i < 4; i++) acc[mt][nt][i] = 0.f;

    int tr = tid >> 3, tj = tid & 7;
    uint32_t tsw = (uint32_t)((tj ^ (tr & 7)) << 4);
    const __nv_bfloat16* gAh = Ah + (size_t)(brow + tr) * K + koff + tj * 8;
    const __nv_bfloat16* gAl = Al + (size_t)(brow + tr) * K + koff + tj * 8;
    const __nv_bfloat16* gBh = Bh + (size_t)(bcol + tr) * K + koff + tj * 8;
    const __nv_bfloat16* gBl = Bl + (size_t)(bcol + tr) * K + koff + tj * 8;

    int sxor = lane & 7;
    uint32_t aRowOff = (uint32_t)((warp_m * 64 + (lane & 15)) * 128);
    int a_cs = lane >> 4;
    uint32_t bRowOff = (uint32_t)((warp_n * 32 + (lane & 7) + ((lane >> 4) << 3)) * 128);
    int b_cs = (lane >> 3) & 1;

    {
        #pragma unroll
        for (int i = 0; i < 8; i++) {
            uint32_t d = smb + (uint32_t)((tr + 16 * i) * 128) + tsw;
            cpasync16(d,          gAh + (size_t)(16 * i) * K);
            cpasync16(d + 16384u, gAl + (size_t)(16 * i) * K);
        }
        #pragma unroll
        for (int i = 0; i < 4; i++) {
            uint32_t d = smb + 32768u + (uint32_t)((tr + 16 * i) * 128) + tsw;
            cpasync16(d,         gBh + (size_t)(16 * i) * K);
            cpasync16(d + 8192u, gBl + (size_t)(16 * i) * K);
        }
        CP_COMMIT();
    }

    for (int ch = 0; ch < nch; ch++) {
        uint32_t sbase = smb + (uint32_t)((ch & 1) ? STAGE_B : 0);
        if (ch + 1 < nch) {
            uint32_t nbase = smb + (uint32_t)(((ch + 1) & 1) ? STAGE_B : 0);
            int k0 = (ch + 1) << 6;
            #pragma unroll
            for (int i = 0; i < 8; i++) {
                uint32_t d = nbase + (uint32_t)((tr + 16 * i) * 128) + tsw;
                cpasync16(d,          gAh + (size_t)(16 * i) * K + k0);
                cpasync16(d + 16384u, gAl + (size_t)(16 * i) * K + k0);
            }
            #pragma unroll
            for (int i = 0; i < 4; i++) {
                uint32_t d = nbase + 32768u + (uint32_t)((tr + 16 * i) * 128) + tsw;
                cpasync16(d,         gBh + (size_t)(16 * i) * K + k0);
                cpasync16(d + 8192u, gBl + (size_t)(16 * i) * K + k0);
            }
            CP_COMMIT();
            CP_WAIT1();
        } else {
            CP_WAIT0();
        }
        __syncthreads();

        #pragma unroll
        for (int kk = 0; kk < 4; kk++) {
            uint32_t bCh = (uint32_t)((((kk * 2 + b_cs) ^ sxor)) << 4);
            uint32_t bAddr = sbase + 32768u + bRowOff + bCh;
            uint32_t bh[8], bl[8];
            ldm4(bh,     bAddr);
            ldm4(bh + 4, bAddr + 2048u);
            ldm4(bl,     bAddr + 8192u);
            ldm4(bl + 4, bAddr + 10240u);
            uint32_t aCh = (uint32_t)((((kk * 2 + a_cs) ^ sxor)) << 4);
            #pragma unroll
            for (int mt = 0; mt < 4; mt++) {
                uint32_t aAddr = sbase + aRowOff + (uint32_t)(mt * 2048) + aCh;
                uint32_t ah[4], al[4];
                ldm4(ah, aAddr);
                ldm4(al, aAddr + 16384u);
                #pragma unroll
                for (int nt = 0; nt < 4; nt++) {
                    mma16816(acc[mt][nt], ah, bh + 2 * nt);
                    mma16816(acc[mt][nt], ah, bl + 2 * nt);
                    mma16816(acc[mt][nt], al, bh + 2 * nt);
                }
            }
        }
        __syncthreads();
    }

    if (EPI == 2) {
        int NOUT = N >> 1;
        #pragma unroll
        for (int mt = 0; mt < 4; mt++) {
            int r0 = brow + warp_m * 64 + mt * 16 + (lane >> 2);
            #pragma unroll
            for (int j = 0; j < 2; j++) {
                int fcol = (bcol >> 1) + warp_n * 16 + j * 8 + (lane & 3) * 2;
                #pragma unroll
                for (int half = 0; half < 2; half++) {
                    int r = r0 + half * 8;
                    float g0 = acc[mt][2*j][half * 2 + 0], u0 = acc[mt][2*j+1][half * 2 + 0];
                    float g1 = acc[mt][2*j][half * 2 + 1], u1 = acc[mt][2*j+1][half * 2 + 1];
                    float y0 = (g0 / (1.f + __expf(-g0))) * u0;
                    float y1 = (g1 / (1.f + __expf(-g1))) * u1;
                    __nv_bfloat16 h0 = __float2bfloat16(y0), h1 = __float2bfloat16(y1);
                    __nv_bfloat16 l0 = __float2bfloat16(y0 - __bfloat162float(h0));
                    __nv_bfloat16 l1 = __float2bfloat16(y1 - __bfloat162float(h1));
                    *(__nv_bfloat162*)(Oh + (size_t)r * NOUT + fcol) = __nv_bfloat162(h0, h1);
                    *(__nv_bfloat162*)(Ol + (size_t)r * NOUT + fcol) = __nv_bfloat162(l0, l1);
                }
            }
        }
    } else {
        #pragma unroll
        for (int mt = 0; mt < 4; mt++) {
            int r0 = brow + warp_m * 64 + mt * 16 + (lane >> 2);
            #pragma unroll
            for (int nt = 0; nt < 4; nt++) {
                int c0 = bcol + warp_n * 32 + nt * 8 + (lane & 3) * 2;
                float* p0 = C + (size_t)r0 * N + c0;
                float* p1 = p0 + 8 * (size_t)N;
                if (EPI == 3) {
                    atomicAdd(p0,     acc[mt][nt][0]);
                    atomicAdd(p0 + 1, acc[mt][nt][1]);
                    atomicAdd(p1,     acc[mt][nt][2]);
                    atomicAdd(p1 + 1, acc[mt][nt][3]);
                } else if (EPI == 1) {
                    p0[0] += acc[mt][nt][0]; p0[1] += acc[mt][nt][1];
                    p1[0] += acc[mt][nt][2]; p1[1] += acc[mt][nt][3];
                } else {
                    *(float2*)p0 = make_float2(acc[mt][nt][0], acc[mt][nt][1]);
                    *(float2*)p1 = make_float2(acc[mt][nt][2], acc[mt][nt][3]);
                }
            }
        }
    }
}

// ---------------- per-layer weight prep: 64x64 tiles, wide I/O ----------
__global__ __launch_bounds__(256)
void wt_prep(const float* __restrict__ wq, const float* __restrict__ wk,
             const float* __restrict__ wv, const float* __restrict__ wo,
             const float* __restrict__ wg, const float* __restrict__ wu,
             const float* __restrict__ wd, int l, int buf) {
    __shared__ float t[64][65];
    int tb = blockIdx.x, tid = threadIdx.x;
    const float* src; __nv_bfloat16 *dh, *dl;
    int K, N, tloc, rowoff = 0, inter = 0;
    if (tb < 375) {
        K = DMODEL;
        dh = g_wqkv_h + (size_t)buf * QKVN * DMODEL;
        dl = g_wqkv_l + (size_t)buf * QKVN * DMODEL;
        if (tb < 225)      { src = wq + (size_t)l * DMODEL * QDIM;  N = QDIM;  tloc = tb; }
        else if (tb < 300) { src = wk + (size_t)l * DMODEL * KVDIM; N = KVDIM; tloc = tb - 225; rowoff = QDIM; }
        else               { src = wv + (size_t)l * DMODEL * KVDIM; N = KVDIM; tloc = tb - 300; rowoff = QDIM + KVDIM; }
    } else if (tb < 600) {
        src = wo + (size_t)l * QDIM * DMODEL; K = QDIM; N = DMODEL; tloc = tb - 375;
        dh = g_wo_h + (size_t)buf * DMODEL * QDIM;
        dl = g_wo_l + (size_t)buf * DMODEL * QDIM;
    } else if (tb < 1800) {
        K = DMODEL; N = FF; inter = 1;
        dh = g_wgu_h + (size_t)buf * 2 * FF * DMODEL;
        dl = g_wgu_l + (size_t)buf * 2 * FF * DMODEL;
        if (tb < 1200) { src = wg + (size_t)l * DMODEL * FF; tloc = tb - 600; }
        else           { src = wu + (size_t)l * DMODEL * FF; tloc = tb - 1200; rowoff = 8; }
    } else {
        src = wd + (size_t)l * FF * DMODEL; K = FF; N = DMODEL; tloc = tb - 1800;
        dh = g_wd_h + (size_t)buf * DMODEL * FF;
        dl = g_wd_l + (size_t)buf * DMODEL * FF;
    }
    int tiles_n = N >> 6;
    int n0 = (tloc % tiles_n) * 64, k0 = (tloc / tiles_n) * 64;

    int trr = tid >> 4, tc4 = (tid & 15) * 4;
    #pragma unroll
    for (int i = 0; i < 4; i++) {
        int r = trr + 16 * i;
        float4 v = *(const float4*)(src + (size_t)(k0 + r) * N + n0 + tc4);
        t[r][tc4] = v.x; t[r][tc4 + 1] = v.y; t[r][tc4 + 2] = v.z; t[r][tc4 + 3] = v.w;
    }
    __syncthreads();

    int kc = (tid & 7) * 8;
    #pragma unroll
    for (int half = 0; half < 2; half++) {
        int rn = (tid >> 3) + half * 32;
        __nv_bfloat16 hb[8], lb[8];
        #pragma unroll
        for (int e = 0; e < 8; e++) {
            float v = t[kc + e][rn];
            __nv_bfloat16 hh = __float2bfloat16(v);
            hb[e] = hh;
            lb[e] = __float2bfloat16(v - __bfloat162float(hh));
        }
        int n = n0 + rn;
        int row = inter ? (((n >> 3) << 4) + (n & 7) + rowoff) : (n + rowoff);
        *(uint4*)(dh + (size_t)row * K + k0 + kc) = *(uint4*)hb;
        *(uint4*)(dl + (size_t)row * K + k0 + kc) = *(uint4*)lb;
    }
}

// ---------------- RMSNorm with fused bf16 split ----------------
__global__ void rmsnorm_split(const float* __restrict__ x, const float* __restrict__ w,
                              __nv_bfloat16* __restrict__ oh, __nv_bfloat16* __restrict__ ol) {
    int row = blockIdx.x;
    const float* xr = x + (size_t)row * DMODEL;
    float ss = 0.f;
    for (int i = threadIdx.x; i < DMODEL; i += blockDim.x) {
        float v = xr[i];
        ss += v * v;
    }
    __shared__ float red[32];
    #pragma unroll
    for (int o = 16; o; o >>= 1) ss += __shfl_xor_sync(0xffffffffu, ss, o);
    int wid = threadIdx.x >> 5, lid = threadIdx.x & 31;
    if (lid == 0) red[wid] = ss;
    __syncthreads();
    if (wid == 0) {
        float v = (lid < (blockDim.x >> 5)) ? red[lid] : 0.f;
        #pragma unroll
        for (int o = 16; o; o >>= 1) v += __shfl_xor_sync(0xffffffffu, v, o);
        if (lid == 0) red[0] = rsqrtf(v / (float)DMODEL + 1e-5f);
    }
    __syncthreads();
    float inv = red[0];
    for (int i = threadIdx.x; i < DMODEL; i += blockDim.x) {
        float y = xr[i] * inv * w[i];
        __nv_bfloat16 h = __float2bfloat16(y);
        oh[(size_t)row * DMODEL + i] = h;
        ol[(size_t)row * DMODEL + i] = __float2bfloat16(y - __bfloat162float(h));
    }
}

// ---------------- rope + split + relayout for MMA attention ------
__global__ void rope_split(const float* __restrict__ qkv, const int* __restrict__ pos) {
    __shared__ float T[64][65];
    int tb = blockIdx.x, tid = threadIdx.x;
    int kind, b, hd, st, off;
    if (tb < 480)      { kind = 0; int r = tb;       b = r / (HQ * 16);  r %= HQ * 16;  hd = r / 16; st = r % 16; off = hd * DH; }
    else if (tb < 640) { kind = 1; int r = tb - 480; b = r / (HKV * 16); r %= HKV * 16; hd = r / 16; st = r % 16; off = QDIM + hd * DH; }
    else               { kind = 2; int r = tb - 640; b = r / (HKV * 16); r %= HKV * 16; hd = r / 16; st = r % 16; off = QDIM + KVDIM + hd * DH; }

    for (int u = tid; u < 1024; u += 256) {
        int r = u >> 4, c4 = (u & 15) * 4;
        float4 v = *(const float4*)(qkv + (size_t)(b * SEQ + st * 64 + r) * QKVN + off + c4);
        T[r][c4] = v.x; T[r][c4 + 1] = v.y; T[r][c4 + 2] = v.z; T[r][c4 + 3] = v.w;
    }
    __syncthreads();

    if (kind <= 1) {
        for (int u = tid; u < 2048; u += 256) {
            int r = u >> 5, d = u & 31;
            float p = (float)pos[b * SEQ + st * 64 + r];
            float ang = p * exp2f((float)d * -0.41524101186098285f);
            float sn, cs;
            sincosf(ang, &sn, &cs);
            float x1 = T[r][d], x2 = T[r][d + 32];
            T[r][d]      = x1 * cs - x2 * sn;
            T[r][d + 32] = x2 * cs + x1 * sn;
        }
        __syncthreads();
    }

    if (kind == 0) {
        __nv_bfloat16* oh = g_qh; __nv_bfloat16* ol = g_ql;
        size_t base = ((size_t)(b * HQ + hd) * SEQ + st * 64);
        for (int u = tid; u < 4096; u += 256) {
            int r = u >> 6, d = u & 63;
            float y = T[r][d] * 0.125f;
            __nv_bfloat16 h = __float2bfloat16(y);
            oh[(base + r) * DH + d] = h;
            ol[(base + r) * DH + d] = __float2bfloat16(y - __bfloat162float(h));
        }
    } else if (kind == 1) {
        size_t base = ((size_t)(b * HKV + hd) * SEQ + st * 64);
        for (int u = tid; u < 4096; u += 256) {
            int r = u >> 6, d = u & 63;
            float y = T[r][d];
            __nv_bfloat16 h = __float2bfloat16(y);
            g_kh[(base + r) * DH + d] = h;
            g_kl[(base + r) * DH + d] = __float2bfloat16(y - __bfloat162float(h));
        }
    } else {
        size_t base = (size_t)(b * HKV + hd) * DH;
        for (int u = tid; u < 4096; u += 256) {
            int d = u >> 6, r = u & 63;
            float y = T[r][d];
            __nv_bfloat16 h = __float2bfloat16(y);
            g_vth[(base + d) * SEQ + st * 64 + r] = h;
            g_vtl[(base + d) * SEQ + st * 64 + r] = __float2bfloat16(y - __bfloat162float(h));
        }
    }
}

// ---------------- MMA flash attention (causal, GQA, longest-first) ----------
#define AT_SMEM (16384 + 2*32768)   // 81920

__global__ __launch_bounds__(128, 2)
void attn_mma(const __nv_bfloat16* __restrict__ qh_, const __nv_bfloat16* __restrict__ ql_,
              const __nv_bfloat16* __restrict__ kh_, const __nv_bfloat16* __restrict__ kl_,
              const __nv_bfloat16* __restrict__ vh_, const __nv_bfloat16* __restrict__ vl_,
              __nv_bfloat16* __restrict__ oh_, __nv_bfloat16* __restrict__ ol_) {
    extern __shared__ char smc[];
    uint32_t smb = smem_u32(smc);
    int qt = (int)gridDim.x - 1 - (int)blockIdx.x;
    int bh = blockIdx.y, b = bh / HQ, hq = bh % HQ, hk = hq / (HQ / HKV);
    int tid = threadIdx.x, wid = tid >> 5, lane = tid & 31;

    int tr = tid >> 3, tj = tid & 7;
    uint32_t tsw = (uint32_t)((tj ^ (tr & 7)) << 4);
    const __nv_bfloat16* gq  = qh_ + ((size_t)(b * HQ + hq) * SEQ + qt * 64 + tr) * DH + tj * 8;
    const __nv_bfloat16* gql = ql_ + ((size_t)(b * HQ + hq) * SEQ + qt * 64 + tr) * DH + tj * 8;
    const __nv_bfloat16* gk  = kh_ + ((size_t)(b * HKV + hk) * SEQ + tr) * DH + tj * 8;
    const __nv_bfloat16* gkl = kl_ + ((size_t)(b * HKV + hk) * SEQ + tr) * DH + tj * 8;
    const __nv_bfloat16* gv  = vh_ + ((size_t)(b * HKV + hk) * DH + tr) * SEQ + tj * 8;
    const __nv_bfloat16* gvl = vl_ + ((size_t)(b * HKV + hk) * DH + tr) * SEQ + tj * 8;

    #pragma unroll
    for (int i = 0; i < 4; i++) {
        uint32_t d = smb + (uint32_t)((tr + 16 * i) * 128) + tsw;
        cpasync16(d,         gq  + (size_t)(16 * i) * DH);
        cpasync16(d + 8192u, gql + (size_t)(16 * i) * DH);
    }
    #pragma unroll
    for (int i = 0; i < 4; i++) {
        uint32_t d = smb + 16384u + (uint32_t)((tr + 16 * i) * 128) + tsw;
        cpasync16(d,          gk  + (size_t)(16 * i) * DH);
        cpasync16(d + 8192u,  gkl + (size_t)(16 * i) * DH);
        cpasync16(d + 16384u, gv  + (size_t)(16 * i) * SEQ);
        cpasync16(d + 24576u, gvl + (size_t)(16 * i) * SEQ);
    }
    CP_COMMIT();

    float o[8][4];
    #pragma unroll
    for (int nt = 0; nt < 8; nt++)
        #pragma unroll
        for (int i = 0; i < 4; i++) o[nt][i] = 0.f;
    float m_a = -1e30f, m_b = -1e30f, l_a = 0.f, l_b = 0.f;

    int sxor = lane & 7;
    uint32_t aRow = (uint32_t)((wid * 16 + (lane & 15)) * 128);
    int a_cs = lane >> 4;
    uint32_t bRow = (uint32_t)(((lane & 7) + ((lane >> 4) << 3)) * 128);
    int b_cs = (lane >> 3) & 1;

    for (int t = 0; t <= qt; t++) {
        if (t + 1 <= qt) {
            uint32_t nb = smb + 16384u + (uint32_t)(((t + 1) & 1) * 32768);
            #pragma unroll
            for (int i = 0; i < 4; i++) {
                uint32_t d = nb + (uint32_t)((tr + 16 * i) * 128) + tsw;
                cpasync16(d,          gk  + (size_t)(t + 1) * 4096 + (size_t)(16 * i) * DH);
                cpasync16(d + 8192u,  gkl + (size_t)(t + 1) * 4096 + (size_t)(16 * i) * DH);
                cpasync16(d + 16384u, gv  + (size_t)(t + 1) * 64 + (size_t)(16 * i) * SEQ);
                cpasync16(d + 24576u, gvl + (size_t)(t + 1) * 64 + (size_t)(16 * i) * SEQ);
            }
            CP_COMMIT();
            CP_WAIT1();
        } else {
            CP_WAIT0();
        }
        __syncthreads();
        uint32_t sb = smb + 16384u + (uint32_t)((t & 1) * 32768);

        float s[8][4];
        #pragma unroll
        for (int nt = 0; nt < 8; nt++)
            #pragma unroll
            for (int i = 0; i < 4; i++) s[nt][i] = 0.f;
        #pragma unroll
        for (int kk = 0; kk < 4; kk++) {
            uint32_t aa = smb + aRow + (uint32_t)(((2 * kk + a_cs) ^ sxor) << 4);
            uint32_t ah[4], al[4];
            ldm4(ah, aa);
            ldm4(al, aa + 8192u);
            #pragma unroll
            for (int np = 0; np < 4; np++) {
                uint32_t ba = sb + bRow + (uint32_t)(np * 2048) + (uint32_t)(((2 * kk + b_cs) ^ sxor) << 4);
                uint32_t kh4[4], kl4[4];
                ldm4(kh4, ba);
                ldm4(kl4, ba + 8192u);
                mma16816(s[2*np],   ah, kh4);
                mma16816(s[2*np],   ah, kl4);
                mma16816(s[2*np],   al, kh4);
                mma16816(s[2*np+1], ah, kh4 + 2);
                mma16816(s[2*np+1], ah, kl4 + 2);
                mma16816(s[2*np+1], al, kh4 + 2);
            }
        }

        if (t == qt) {
            int iA = wid * 16 + (lane >> 2);
            int jb = (lane & 3) * 2;
            #pragma unroll
            for (int nt = 0; nt < 8; nt++) {
                int j0 = nt * 8 + jb;
                if (j0     > iA)     s[nt][0] = -1e30f;
                if (j0 + 1 > iA)     s[nt][1] = -1e30f;
                if (j0     > iA + 8) s[nt][2] = -1e30f;
                if (j0 + 1 > iA + 8) s[nt][3] = -1e30f;
            }
        }

        float mA = -1e30f, mB = -1e30f;
        #pragma unroll
        for (int nt = 0; nt < 8; nt++) {
            mA = fmaxf(mA, fmaxf(s[nt][0], s[nt][1]));
            mB = fmaxf(mB, fmaxf(s[nt][2], s[nt][3]));
        }
        mA = fmaxf(mA, __shfl_xor_sync(0xffffffffu, mA, 1));
        mA = fmaxf(mA, __shfl_xor_sync(0xffffffffu, mA, 2));
        mB = fmaxf(mB, __shfl_xor_sync(0xffffffffu, mB, 1));
        mB = fmaxf(mB, __shfl_xor_sync(0xffffffffu, mB, 2));
        float mnA = fmaxf(m_a, mA), mnB = fmaxf(m_b, mB);
        float scA = __expf(m_a - mnA), scB = __expf(m_b - mnB);
        float suA = 0.f, suB = 0.f;
        #pragma unroll
        for (int nt = 0; nt < 8; nt++) {
            s[nt][0] = __expf(s[nt][0] - mnA); suA += s[nt][0];
            s[nt][1] = __expf(s[nt][1] - mnA); suA += s[nt][1];
            s[nt][2] = __expf(s[nt][2] - mnB); suB += s[nt][2];
            s[nt][3] = __expf(s[nt][3] - mnB); suB += s[nt][3];
        }
        suA += __shfl_xor_sync(0xffffffffu, suA, 1);
        suA += __shfl_xor_sync(0xffffffffu, suA, 2);
        suB += __shfl_xor_sync(0xffffffffu, suB, 1);
        suB += __shfl_xor_sync(0xffffffffu, suB, 2);
        l_a = l_a * scA + suA;
        l_b = l_b * scB + suB;
        m_a = mnA; m_b = mnB;
        #pragma unroll
        for (int nt = 0; nt < 8; nt++) {
            o[nt][0] *= scA; o[nt][1] *= scA;
            o[nt][2] *= scB; o[nt][3] *= scB;
        }

        #pragma unroll
        for (int kt = 0; kt < 4; kt++) {
            float p00 = s[2*kt][0],   p01 = s[2*kt][1],   p02 = s[2*kt][2],   p03 = s[2*kt][3];
            float p10 = s[2*kt+1][0], p11 = s[2*kt+1][1], p12 = s[2*kt+1][2], p13 = s[2*kt+1][3];
            uint32_t aPh[4], aPl[4];
            aPh[0] = packbf(p00, p01);
            aPh[1] = packbf(p02, p03);
            aPh[2] = packbf(p10, p11);
            aPh[3] = packbf(p12, p13);
            __nv_bfloat162* hp;
            hp = (__nv_bfloat162*)&aPh[0];
            aPl[0] = packbf(p00 - __bfloat162float(hp->x), p01 - __bfloat162float(hp->y));
            hp = (__nv_bfloat162*)&aPh[1];
            aPl[1] = packbf(p02 - __bfloat162float(hp->x), p03 - __bfloat162float(hp->y));
            hp = (__nv_bfloat162*)&aPh[2];
            aPl[2] = packbf(p10 - __bfloat162float(hp->x), p11 - __bfloat162float(hp->y));
            hp = (__nv_bfloat162*)&aPh[3];
            aPl[3] = packbf(p12 - __bfloat162float(hp->x), p13 - __bfloat162float(hp->y));
            #pragma unroll
            for (int np = 0; np < 4; np++) {
                uint32_t va = sb + 16384u + bRow + (uint32_t)(np * 2048) + (uint32_t)(((2 * kt + b_cs) ^ sxor) << 4);
                uint32_t vh4[4], vl4[4];
                ldm4(vh4, va);
                ldm4(vl4, va + 8192u);
                mma16816(o[2*np],   aPh, vh4);
                mma16816(o[2*np],   aPh, vl4);
                mma16816(o[2*np],   aPl, vh4);
                mma16816(o[2*np+1], aPh, vh4 + 2);
                mma16816(o[2*np+1], aPh, vl4 + 2);
                mma16816(o[2*np+1], aPl, vh4 + 2);
            }
        }
        __syncthreads();
    }

    float ivA = 1.f / l_a, ivB = 1.f / l_b;
    size_t rA = (size_t)(b * SEQ + qt * 64 + wid * 16 + (lane >> 2));
    size_t rB = rA + 8;
    int cb = hq * DH + (lane & 3) * 2;
    #pragma unroll
    for (int nt = 0; nt < 8; nt++) {
        int c = cb + nt * 8;
        float y0 = o[nt][0] * ivA, y1 = o[nt][1] * ivA;
        __nv_bfloat16 h0 = __float2bfloat16(y0), h1 = __float2bfloat16(y1);
        *(__nv_bfloat162*)(oh_ + rA * QDIM + c) = __nv_bfloat162(h0, h1);
        *(__nv_bfloat162*)(ol_ + rA * QDIM + c) = __nv_bfloat162(
            __float2bfloat16(y0 - __bfloat162float(h0)),
            __float2bfloat16(y1 - __bfloat162float(h1)));
        float y2 = o[nt][2] * ivB, y3 = o[nt][3] * ivB;
        __nv_bfloat16 h2 = __float2bfloat16(y2), h3 = __float2bfloat16(y3);
        *(__nv_bfloat162*)(oh_ + rB * QDIM + c) = __nv_bfloat162(h2, h3);
        *(__nv_bfloat162*)(ol_ + rB * QDIM + c) = __nv_bfloat162(
            __float2bfloat16(y2 - __bfloat162float(h2)),
            __float2bfloat16(y3 - __bfloat162float(h3)));
    }
}

// ---------------- host driver ----------------
extern "C" void kernel_launch(void* const* d_in, const int* in_sizes, int n_in,
                              void* d_out, int out_size) {
    (void)in_sizes; (void)n_in; (void)out_size;
    const float* prefix = (const float*)d_in[0];
    const float* ln1    = (const float*)d_in[1];
    const float* wq     = (const float*)d_in[2];
    const float* wk     = (const float*)d_in[3];
    const float* wv     = (const float*)d_in[4];
    const float* wo     = (const float*)d_in[5];
    const float* ln2    = (const float*)d_in[6];
    const float* wg     = (const float*)d_in[7];
    const float* wu     = (const float*)d_in[8];
    const float* wd     = (const float*)d_in[9];
    const int*   pos    = (const int*)d_in[11];
    float* h = (float*)d_out;

    __nv_bfloat16 *hn_h, *hn_l, *at_h, *at_l, *ac_h, *ac_l;
    __nv_bfloat16 *qh, *ql, *kh, *kl, *vth, *vtl;
    __nv_bfloat16 *wqkv_h, *wqkv_l, *wo_h, *wo_l, *wgu_h, *wgu_l, *wd_h, *wd_l;
    float *qkv;
    cudaGetSymbolAddress((void**)&hn_h, g_hn_h);
    cudaGetSymbolAddress((void**)&hn_l, g_hn_l);
    cudaGetSymbolAddress((void**)&qkv,  g_qkv);
    cudaGetSymbolAddress((void**)&at_h, g_at_h);
    cudaGetSymbolAddress((void**)&at_l, g_at_l);
    cudaGetSymbolAddress((void**)&ac_h, g_ac_h);
    cudaGetSymbolAddress((void**)&ac_l, g_ac_l);
    cudaGetSymbolAddress((void**)&qh,  g_qh);
    cudaGetSymbolAddress((void**)&ql,  g_ql);
    cudaGetSymbolAddress((void**)&kh,  g_kh);
    cudaGetSymbolAddress((void**)&kl,  g_kl);
    cudaGetSymbolAddress((void**)&vth, g_vth);
    cudaGetSymbolAddress((void**)&vtl, g_vtl);
    cudaGetSymbolAddress((void**)&wqkv_h, g_wqkv_h);
    cudaGetSymbolAddress((void**)&wqkv_l, g_wqkv_l);
    cudaGetSymbolAddress((void**)&wo_h,   g_wo_h);
    cudaGetSymbolAddress((void**)&wo_l,   g_wo_l);
    cudaGetSymbolAddress((void**)&wgu_h,  g_wgu_h);
    cudaGetSymbolAddress((void**)&wgu_l,  g_wgu_l);
    cudaGetSymbolAddress((void**)&wd_h,   g_wd_h);
    cudaGetSymbolAddress((void**)&wd_l,   g_wd_l);

    cudaFuncSetAttribute(mma_gemm<0>, cudaFuncAttributeMaxDynamicSharedMemorySize, GEMM_SMEM);
    cudaFuncSetAttribute(mma_gemm<2>, cudaFuncAttributeMaxDynamicSharedMemorySize, GEMM_SMEM);
    cudaFuncSetAttribute(mma_gemm<3>, cudaFuncAttributeMaxDynamicSharedMemorySize, GEMM_SMEM);
    cudaFuncSetAttribute(attn_mma,    cudaFuncAttributeMaxDynamicSharedMemorySize, AT_SMEM);

    // Side stream + events, created ONCE on the first (uncaptured) call.
    // Stream/event CREATION is illegal during global-mode graph capture;
    // record/wait are capture-legal and become graph edges. The launch
    // sequence per call is identical, so determinism is preserved.
    static cudaStream_t s2 = nullptr;
    static cudaEvent_t evF[NLAYERS], evJ[NLAYERS];
    if (s2 == nullptr) {
        cudaStreamCreateWithFlags(&s2, cudaStreamNonBlocking);
        for (int l = 0; l < NLAYERS; l++) {
            cudaEventCreateWithFlags(&evF[l], cudaEventDisableTiming);
            cudaEventCreateWithFlags(&evJ[l], cudaEventDisableTiming);
        }
    }

    cudaMemcpyAsync(h, prefix, (size_t)MROWS * DMODEL * sizeof(float),
                    cudaMemcpyDeviceToDevice, 0);

    // layer-0 weights on the main stream
    wt_prep<<<2400, 256>>>(wq, wk, wv, wo, wg, wu, wd, 0, 0);

    for (int l = 0; l < NLAYERS; l++) {
        int buf = l & 1;
        // fork: prep layer l+1 weights into the other buffer on s2
        if (l + 1 < NLAYERS) {
            cudaEventRecord(evF[l], 0);
            cudaStreamWaitEvent(s2, evF[l], 0);
            wt_prep<<<2400, 256, 0, s2>>>(wq, wk, wv, wo, wg, wu, wd, l + 1, (l + 1) & 1);
            cudaEventRecord(evJ[l], s2);
        }

        const __nv_bfloat16* bwqkv_h = wqkv_h + (size_t)buf * QKVN * DMODEL;
        const __nv_bfloat16* bwqkv_l = wqkv_l + (size_t)buf * QKVN * DMODEL;
        const __nv_bfloat16* bwo_h   = wo_h + (size_t)buf * DMODEL * QDIM;
        const __nv_bfloat16* bwo_l   = wo_l + (size_t)buf * DMODEL * QDIM;
        const __nv_bfloat16* bwgu_h  = wgu_h + (size_t)buf * 2 * FF * DMODEL;
        const __nv_bfloat16* bwgu_l  = wgu_l + (size_t)buf * 2 * FF * DMODEL;
        const __nv_bfloat16* bwd_h   = wd_h + (size_t)buf * DMODEL * FF;
        const __nv_bfloat16* bwd_l   = wd_l + (size_t)buf * DMODEL * FF;

        // attention block
        rmsnorm_split<<<MROWS, 256>>>(h, ln1 + (size_t)l * DMODEL, hn_h, hn_l);
        mma_gemm<0><<<dim3(QKVN / 64, MROWS / 128), 128, GEMM_SMEM>>>(
            hn_h, hn_l, bwqkv_h, bwqkv_l, qkv, nullptr, nullptr, QKVN, DMODEL);
        rope_split<<<800, 256>>>(qkv, pos);
        attn_mma<<<dim3(SEQ / 64, BATCH * HQ), 128, AT_SMEM>>>(
            qh, ql, kh, kl, vth, vtl, at_h, at_l);
        mma_gemm<3><<<dim3(DMODEL / 64, MROWS / 128, 2), 128, GEMM_SMEM>>>(
            at_h, at_l, bwo_h, bwo_l, h, nullptr, nullptr, DMODEL, QDIM);

        // mlp block
        rmsnorm_split<<<MROWS, 256>>>(h, ln2 + (size_t)l * DMODEL, hn_h, hn_l);
        mma_gemm<2><<<dim3(2 * FF / 64, MROWS / 128), 128, GEMM_SMEM>>>(
            hn_h, hn_l, bwgu_h, bwgu_l, nullptr, ac_h, ac_l, 2 * FF, DMODEL);
        mma_gemm<3><<<dim3(DMODEL / 64, MROWS / 128, 2), 128, GEMM_SMEM>>>(
            ac_h, ac_l, bwd_h, bwd_l, h, nullptr, nullptr, DMODEL, FF);

        // join: next layer's weights must be ready before its first GEMM
        if (l + 1 < NLAYERS) cudaStreamWaitEvent(0, evJ[l], 0);
    }
}